// round 10
// baseline (speedup 1.0000x reference)
#include <cuda_runtime.h>
#include <cuda_bf16.h>
#include <cstdint>

#define NRES 384
#define CH 128
#define NN (NRES*NRES)
#define EPSF 1e-5f
#define KS2 768           // triangle operand row: [hi(384)|lo(384)]
#define KP2 256           // proj/out row: [hi(128)|lo(128)]
#define BK 16
#define LDW 24            // bf16 per padded smem row (48B)

// ---- scratch (device globals; no allocation) ----
__device__ __nv_bfloat16 g_as[(size_t)CH*NRES*KS2];
__device__ __nv_bfloat16 g_bs[(size_t)CH*NRES*KS2];
__device__ __nv_bfloat16 g_zs[(size_t)NN*KP2];
__device__ __nv_bfloat16 g_xs[(size_t)NN*KP2];
__device__ __nv_bfloat16 g_ws[(size_t)6*CH*KP2];
__device__ float g_gate[(size_t)NN*CH];
__device__ float g_xt[(size_t)CH*NN];

__device__ __forceinline__ float sigf(float x){ return 1.f/(1.f+__expf(-x)); }

__device__ __forceinline__ uint32_t s2u(const void* p){
    uint32_t a;
    asm("{ .reg .u64 t; cvta.to.shared.u64 t, %1; cvt.u32.u64 %0, t; }" : "=r"(a) : "l"(p));
    return a;
}
__device__ __forceinline__ void ldsm4(uint32_t &r0,uint32_t &r1,uint32_t &r2,uint32_t &r3,uint32_t a){
    asm volatile("ldmatrix.sync.aligned.m8n8.x4.shared.b16 {%0,%1,%2,%3}, [%4];"
        : "=r"(r0),"=r"(r1),"=r"(r2),"=r"(r3) : "r"(a));
}
__device__ __forceinline__ void mma16816(float* d, const uint32_t* a, const uint32_t* b){
    asm volatile("mma.sync.aligned.m16n8k16.row.col.f32.bf16.bf16.f32 "
        "{%0,%1,%2,%3}, {%4,%5,%6,%7}, {%8,%9}, {%0,%1,%2,%3};"
        : "+f"(d[0]),"+f"(d[1]),"+f"(d[2]),"+f"(d[3])
        : "r"(a[0]),"r"(a[1]),"r"(a[2]),"r"(a[3]), "r"(b[0]),"r"(b[1]));
}
__device__ __forceinline__ void cpa(uint32_t d, const void* s){
    asm volatile("cp.async.ca.shared.global [%0], [%1], 16;" :: "r"(d), "l"(s) : "memory");
}
__device__ __forceinline__ void cp_commit(){ asm volatile("cp.async.commit_group;" ::: "memory"); }
template<int N> __device__ __forceinline__ void cp_wait(){ asm volatile("cp.async.wait_group %0;" :: "n"(N) : "memory"); }

// B fragments: 4 n8k16 tiles (32 n-rows) from padded smem (LDW bf16/row), k16 chunk
__device__ __forceinline__ void ldB(uint32_t base, int wn, int lane, uint32_t bf[4][2]){
    int kc = ((lane>>3)&1)*8;
    #pragma unroll
    for (int nf2=0; nf2<2; ++nf2){
        int nrow = wn*32 + nf2*16 + (lane&7) + ((lane>>4)<<3);
        uint32_t r0,r1,r2,r3;
        ldsm4(r0,r1,r2,r3, base + (uint32_t)(nrow*LDW + kc)*2);
        bf[nf2*2+0][0]=r0; bf[nf2*2+0][1]=r1;
        bf[nf2*2+1][0]=r2; bf[nf2*2+1][1]=r3;
    }
}

// ---- split 6 weights into bf16 [Wh|Wl] ----
__global__ void wsplit_kernel(const float* w0, const float* w1, const float* w2,
                              const float* w3, const float* w4, const float* w5){
    const float* srcs[6] = {w0,w1,w2,w3,w4,w5};
    const float* W = srcs[blockIdx.x];
    __nv_bfloat16* dst = g_ws + (size_t)blockIdx.x*CH*KP2;
    for (int it=0; it<64; ++it){
        int idx = threadIdx.x + it*256;
        int o = idx>>7, k = idx&127;
        float v = W[idx];
        __nv_bfloat16 hi = __float2bfloat16(v);
        __nv_bfloat16 lo = __float2bfloat16(v - __bfloat162float(hi));
        dst[(size_t)o*KP2 + k]       = hi;
        dst[(size_t)o*KP2 + 128 + k] = lo;
    }
}

// ---- LN(z) -> split bf16 rows [zh|zl] ----
__global__ __launch_bounds__(256)
void ln_split_kernel(const float* __restrict__ z,
                     const float* __restrict__ lnw, const float* __restrict__ lnb){
    int tid=threadIdx.x, wid=tid>>5, lane=tid&31;
    size_t row = (size_t)blockIdx.x*8 + wid;
    float4 v = *(const float4*)(z + row*CH + lane*4);
    float s = v.x+v.y+v.z+v.w;
    float q = v.x*v.x+v.y*v.y+v.z*v.z+v.w*v.w;
    #pragma unroll
    for (int o=16;o>0;o>>=1){ s+=__shfl_xor_sync(0xffffffffu,s,o); q+=__shfl_xor_sync(0xffffffffu,q,o); }
    float mu=s*(1.f/128.f), var=q*(1.f/128.f)-mu*mu;
    float rs=rsqrtf(fmaxf(var,0.f)+EPSF);
    float4 w4 = *(const float4*)(lnw + lane*4);
    float4 b4 = *(const float4*)(lnb + lane*4);
    float n[4] = {(v.x-mu)*rs*w4.x+b4.x, (v.y-mu)*rs*w4.y+b4.y,
                  (v.z-mu)*rs*w4.z+b4.z, (v.w-mu)*rs*w4.w+b4.w};
    __nv_bfloat16 hi[4], lo[4];
    #pragma unroll
    for (int j=0;j<4;++j){
        hi[j] = __float2bfloat16(n[j]);
        lo[j] = __float2bfloat16(n[j]-__bfloat162float(hi[j]));
    }
    __nv_bfloat16* d = g_zs + row*KP2 + lane*4;
    *(__nv_bfloat162*)(d)     = __nv_bfloat162{hi[0],hi[1]};
    *(__nv_bfloat162*)(d+2)   = __nv_bfloat162{hi[2],hi[3]};
    *(__nv_bfloat162*)(d+128) = __nv_bfloat162{lo[0],lo[1]};
    *(__nv_bfloat162*)(d+130) = __nv_bfloat162{lo[2],lo[3]};
}

// ================= projmma: 64-row tiles, grid (2304,3), 3-stage pipe =================
// stage regions (bytes): Zh 0, Zl 3072, Gh 6144, Gl 12288, Ph 18432, Pl 24576
#define PSTEP3 30720u
#define NCH_P 8

__device__ __forceinline__ void proj_issue(int tid, int c, int st, bool hasP,
    uint32_t sb, const __nv_bfloat16* Az, const __nv_bfloat16* WG, const __nv_bfloat16* WP){
    uint32_t bofs = (uint32_t)st*PSTEP3;
    {   // Zh (threads 0-127) / Zl (threads 128-255)
        int r2 = (tid&127)>>1, sg = tid&1;
        int loq = tid>>7;   // 0: hi, 1: lo
        uint32_t off = sb + bofs + (uint32_t)loq*3072u + (uint32_t)(r2*48 + sg*16);
        cpa(off, Az + (size_t)r2*KP2 + loq*128 + c*BK + sg*8);
    }
    {   // weights: 128 rows x 2 segs per region
        int row = tid>>1, sg = tid&1;
        uint32_t off = (uint32_t)(row*48 + sg*16);
        size_t gof = (size_t)row*KP2 + c*BK + sg*8;
        cpa(sb + bofs + 6144u  + off, WG + gof);
        cpa(sb + bofs + 12288u + off, WG + gof + 128);
        if (hasP){
            cpa(sb + bofs + 18432u + off, WP + gof);
            cpa(sb + bofs + 24576u + off, WP + gof + 128);
        }
    }
    cp_commit();
}

__global__ __launch_bounds__(256,2)
void projmma_kernel(const float* __restrict__ mask_,
                    const float* __restrict__ agb, const float* __restrict__ apb,
                    const float* __restrict__ bgb, const float* __restrict__ bpb,
                    const float* __restrict__ gb_)
{
    extern __shared__ char sm[];
    uint32_t sb = s2u(sm);
    float* ot = (float*)sm;

    int tid=threadIdx.x, wid=tid>>5, lane=tid&31;
    int wm=wid&1, wn=wid>>1;
    int t2 = blockIdx.x, ph = blockIdx.y;
    bool hasP = ph<2;
    const __nv_bfloat16* WG = g_ws + (size_t)(hasP ? 2*ph : 4)*CH*KP2;
    const __nv_bfloat16* WP = g_ws + (size_t)(hasP ? 2*ph+1 : 4)*CH*KP2;
    const float* GBp = (ph==0)?agb:((ph==1)?bgb:gb_);
    const float* PBp = (ph==0)?apb:bpb;
    const __nv_bfloat16* Az = g_zs + (size_t)t2*64*KP2;

    float accG[2][4][4], accP[2][4][4];
    #pragma unroll
    for (int mf=0;mf<2;++mf)
        #pragma unroll
        for (int nf=0;nf<4;++nf)
            #pragma unroll
            for (int r=0;r<4;++r){ accG[mf][nf][r]=0.f; accP[mf][nf][r]=0.f; }

    proj_issue(tid, 0, 0, hasP, sb, Az, WG, WP);
    proj_issue(tid, 1, 1, hasP, sb, Az, WG, WP);

    for (int c=0; c<NCH_P; ++c){
        if (c+1<NCH_P) cp_wait<1>(); else cp_wait<0>();
        __syncthreads();
        if (c+2<NCH_P) proj_issue(tid, c+2, (c+2)%3, hasP, sb, Az, WG, WP);
        uint32_t bofs = sb + (uint32_t)(c%3)*PSTEP3;

        uint32_t ah[2][4], al[2][4];
        #pragma unroll
        for (int mf=0; mf<2; ++mf){
            int row = wm*32 + mf*16 + (lane&15);
            int kc  = (lane>>4)*8;
            uint32_t ro = (uint32_t)(row*LDW + kc)*2;
            ldsm4(ah[mf][0],ah[mf][1],ah[mf][2],ah[mf][3], bofs + ro);
            ldsm4(al[mf][0],al[mf][1],al[mf][2],al[mf][3], bofs + 3072u + ro);
        }
        uint32_t bf[4][2];
        ldB(bofs + 6144u, wn, lane, bf);   // Gh
        #pragma unroll
        for (int mf=0; mf<2; ++mf)
            #pragma unroll
            for (int nf=0; nf<4; ++nf){
                mma16816(accG[mf][nf], ah[mf], bf[nf]);
                mma16816(accG[mf][nf], al[mf], bf[nf]);
            }
        ldB(bofs + 12288u, wn, lane, bf);  // Gl
        #pragma unroll
        for (int mf=0; mf<2; ++mf)
            #pragma unroll
            for (int nf=0; nf<4; ++nf)
                mma16816(accG[mf][nf], ah[mf], bf[nf]);
        if (hasP){
            ldB(bofs + 18432u, wn, lane, bf);  // Ph
            #pragma unroll
            for (int mf=0; mf<2; ++mf)
                #pragma unroll
                for (int nf=0; nf<4; ++nf){
                    mma16816(accP[mf][nf], ah[mf], bf[nf]);
                    mma16816(accP[mf][nf], al[mf], bf[nf]);
                }
            ldB(bofs + 24576u, wn, lane, bf);  // Pl
            #pragma unroll
            for (int mf=0; mf<2; ++mf)
                #pragma unroll
                for (int nf=0; nf<4; ++nf)
                    mma16816(accP[mf][nf], ah[mf], bf[nf]);
        }
    }
    __syncthreads();

    if (hasP){
        __nv_bfloat16* dst = ph ? g_bs : g_as;
        int i_idx = t2/6, k0 = (t2%6)*64;
        #pragma unroll
        for (int mf=0; mf<2; ++mf)
            #pragma unroll
            for (int nf=0; nf<4; ++nf){
                int col = wn*32 + nf*8 + (lane&3)*2;
                int row = wm*32 + mf*16 + (lane>>2);
                float mk0 = __ldg(mask_ + t2*64 + row);
                float mk1 = __ldg(mask_ + t2*64 + row + 8);
                float g0=__ldg(GBp+col), g1=__ldg(GBp+col+1);
                float p0=__ldg(PBp+col), p1=__ldg(PBp+col+1);
                ot[col*68+row]       = mk0*sigf(accG[mf][nf][0]+g0)*(accP[mf][nf][0]+p0);
                ot[(col+1)*68+row]   = mk0*sigf(accG[mf][nf][1]+g1)*(accP[mf][nf][1]+p1);
                ot[col*68+row+8]     = mk1*sigf(accG[mf][nf][2]+g0)*(accP[mf][nf][2]+p0);
                ot[(col+1)*68+row+8] = mk1*sigf(accG[mf][nf][3]+g1)*(accP[mf][nf][3]+p1);
            }
        __syncthreads();
        #pragma unroll
        for (int it2=0; it2<32; ++it2){
            int f = tid + it2*256;
            int r = f&63, o = f>>6;
            float v = ot[o*68 + r];
            __nv_bfloat16 hi = __float2bfloat16(v);
            __nv_bfloat16 lo = __float2bfloat16(v - __bfloat162float(hi));
            size_t base = (size_t)o*(NRES*KS2) + (size_t)i_idx*KS2 + (k0 + r);
            dst[base]       = hi;
            dst[base + 384] = lo;
        }
    } else {
        #pragma unroll
        for (int mf=0; mf<2; ++mf)
            #pragma unroll
            for (int nf=0; nf<4; ++nf){
                int col = wn*32 + nf*8 + (lane&3)*2;
                int row = wm*32 + mf*16 + (lane>>2);
                size_t R0 = (size_t)t2*64 + row;
                float g0=__ldg(GBp+col), g1=__ldg(GBp+col+1);
                *(float2*)(g_gate + R0*CH + col) =
                    make_float2(sigf(accG[mf][nf][0]+g0), sigf(accG[mf][nf][1]+g1));
                *(float2*)(g_gate + (R0+8)*CH + col) =
                    make_float2(sigf(accG[mf][nf][2]+g0), sigf(accG[mf][nf][3]+g1));
            }
    }
}

// ================= tri: per (h,i-tile,j-tile), 3-stage pipe =================
// stage regions: Ah 0, Al 6144, Bh 12288, Bl 18432
#define TSTEP3 24576u
#define NCH_T 24

__device__ __forceinline__ void tri_issue(int tid, int c, int st,
    const __nv_bfloat16* Ag, const __nv_bfloat16* Bg, uint32_t sb){
    int row = tid>>1, sg = tid&1;
    uint32_t bofs = (uint32_t)st*TSTEP3 + (uint32_t)(row*48 + sg*16);
    const __nv_bfloat16* ar = Ag + (size_t)row*KS2 + c*BK + sg*8;
    cpa(sb + bofs,           ar);
    cpa(sb + 6144u + bofs,   ar+384);
    const __nv_bfloat16* br = Bg + (size_t)row*KS2 + c*BK + sg*8;
    cpa(sb + 12288u + bofs,  br);
    cpa(sb + 18432u + bofs,  br+384);
    cp_commit();
}

__global__ __launch_bounds__(256,2)
void tri_mma_kernel(){
    extern __shared__ char sm[];
    uint32_t sb = s2u(sm);

    int tid = threadIdx.x;
    int wid = tid>>5, lane = tid&31;
    int wm = wid & 1, wn = wid >> 1;
    int h = blockIdx.z, i0 = blockIdx.y*128, j0 = blockIdx.x*128;

    const __nv_bfloat16* Ag = g_as + ((size_t)h*NRES + i0)*KS2;
    const __nv_bfloat16* Bg = g_bs + ((size_t)h*NRES + j0)*KS2;

    float acc[4][4][4];
    #pragma unroll
    for (int mf=0;mf<4;++mf)
        #pragma unroll
        for (int nf=0;nf<4;++nf)
            #pragma unroll
            for (int r=0;r<4;++r) acc[mf][nf][r]=0.f;

    tri_issue(tid, 0, 0, Ag, Bg, sb);
    tri_issue(tid, 1, 1, Ag, Bg, sb);

    for (int c=0; c<NCH_T; ++c){
        if (c+1<NCH_T) cp_wait<1>(); else cp_wait<0>();
        __syncthreads();
        if (c+2<NCH_T) tri_issue(tid, c+2, (c+2)%3, Ag, Bg, sb);
        uint32_t bofs = sb + (uint32_t)(c%3)*TSTEP3;

        uint32_t ah[4][4];
        #pragma unroll
        for (int mf=0; mf<4; ++mf){
            int row = wm*64 + mf*16 + (lane&15);
            int kc  = (lane>>4)*8;
            ldsm4(ah[mf][0],ah[mf][1],ah[mf][2],ah[mf][3], bofs + (uint32_t)(row*LDW + kc)*2);
        }
        uint32_t bh[4][2];
        ldB(bofs + 12288u, wn, lane, bh);   // Bh
        #pragma unroll
        for (int mf=0; mf<4; ++mf)
            #pragma unroll
            for (int nf=0; nf<4; ++nf)
                mma16816(acc[mf][nf], ah[mf], bh[nf]);
        {
            uint32_t bl[4][2];
            ldB(bofs + 18432u, wn, lane, bl);  // Bl
            #pragma unroll
            for (int mf=0; mf<4; ++mf)
                #pragma unroll
                for (int nf=0; nf<4; ++nf)
                    mma16816(acc[mf][nf], ah[mf], bl[nf]);
        }
        #pragma unroll
        for (int mf=0; mf<4; ++mf){   // reuse ah regs for Al
            int row = wm*64 + mf*16 + (lane&15);
            int kc  = (lane>>4)*8;
            ldsm4(ah[mf][0],ah[mf][1],ah[mf][2],ah[mf][3], bofs + 6144u + (uint32_t)(row*LDW + kc)*2);
        }
        #pragma unroll
        for (int mf=0; mf<4; ++mf)
            #pragma unroll
            for (int nf=0; nf<4; ++nf)
                mma16816(acc[mf][nf], ah[mf], bh[nf]);
    }

    float* X = g_xt + (size_t)h*NN;
    #pragma unroll
    for (int mf=0; mf<4; ++mf){
        #pragma unroll
        for (int nf=0; nf<4; ++nf){
            int row = i0 + wm*64 + mf*16 + (lane>>2);
            int col = j0 + wn*32 + nf*8 + (lane&3)*2;
            *(float2*)(X + (size_t)row*NRES + col)     = make_float2(acc[mf][nf][0], acc[mf][nf][1]);
            *(float2*)(X + (size_t)(row+8)*NRES + col) = make_float2(acc[mf][nf][2], acc[mf][nf][3]);
        }
    }
}

// ---- LN over h of x -> split bf16 rows [xh|xl] ----
__global__ __launch_bounds__(256)
void ln_out_split_kernel(const float* __restrict__ low, const float* __restrict__ lob){
    __shared__ float xs[128*66];
    __shared__ float mu_s[64], rs_s[64];
    __shared__ float low_s[128], lob_s[128];
    int tid=threadIdx.x;
    int row0 = blockIdx.x*64;
    if (tid<128){ low_s[tid]=low[tid]; lob_s[tid]=lob[tid]; }
    #pragma unroll
    for (int it=0; it<32; ++it){
        int f = tid + it*256;
        int r = f&63, h = f>>6;
        xs[h*66 + r] = g_xt[(size_t)h*NN + row0 + r];
    }
    __syncthreads();
    int lane=tid&31, wid=tid>>5;
    #pragma unroll
    for (int rr=0;rr<8;++rr){
        int r = wid*8+rr;
        float s=0.f,q=0.f;
        #pragma unroll
        for (int m=0;m<4;++m){ float x=xs[(lane+32*m)*66 + r]; s+=x; q+=x*x; }
        #pragma unroll
        for (int o=16;o>0;o>>=1){ s+=__shfl_xor_sync(0xffffffffu,s,o); q+=__shfl_xor_sync(0xffffffffu,q,o); }
        if (lane==0){
            float mu=s*(1.f/128.f), var=q*(1.f/128.f)-mu*mu;
            mu_s[r]=mu; rs_s[r]=rsqrtf(fmaxf(var,0.f)+EPSF);
        }
    }
    __syncthreads();
    #pragma unroll
    for (int it=0; it<16; ++it){
        int f = tid + it*256;
        int r = f>>6, h2 = (f&63)*2;
        float mu=mu_s[r], rs=rs_s[r];
        float x0 = (xs[(h2+0)*66+r]-mu)*rs*low_s[h2+0]+lob_s[h2+0];
        float x1 = (xs[(h2+1)*66+r]-mu)*rs*low_s[h2+1]+lob_s[h2+1];
        __nv_bfloat16 h0=__float2bfloat16(x0), h1=__float2bfloat16(x1);
        __nv_bfloat16 l0=__float2bfloat16(x0-__bfloat162float(h0));
        __nv_bfloat16 l1=__float2bfloat16(x1-__bfloat162float(h1));
        __nv_bfloat16* d = g_xs + (size_t)(row0+r)*KP2 + h2;
        *(__nv_bfloat162*)(d)     = __nv_bfloat162{h0,h1};
        *(__nv_bfloat162*)(d+128) = __nv_bfloat162{l0,l1};
    }
}

// ================= outmma: out = gate * (xn @ z_w^T + z_b), 3-stage pipe =================
// stage regions: Xh 0, Xl 3072, Wh 6144, Wl 12288
#define OSTEP3 18432u

__device__ __forceinline__ void out_issue(int tid, int c, int st,
    uint32_t sb, const __nv_bfloat16* Ax, const __nv_bfloat16* W){
    uint32_t bofs = (uint32_t)st*OSTEP3;
    {
        int r2 = (tid&127)>>1, sg = tid&1;
        int loq = tid>>7;
        uint32_t off = sb + bofs + (uint32_t)loq*3072u + (uint32_t)(r2*48 + sg*16);
        cpa(off, Ax + (size_t)r2*KP2 + loq*128 + c*BK + sg*8);
    }
    {
        int row = tid>>1, sg = tid&1;
        uint32_t off = (uint32_t)(row*48 + sg*16);
        size_t gof = (size_t)row*KP2 + c*BK + sg*8;
        cpa(sb + bofs + 6144u  + off, W + gof);
        cpa(sb + bofs + 12288u + off, W + gof + 128);
    }
    cp_commit();
}

__global__ __launch_bounds__(256,2)
void outmma_kernel(const float* __restrict__ zb, float* __restrict__ out)
{
    extern __shared__ char sm[];
    uint32_t sb = s2u(sm);

    int tid=threadIdx.x, wid=tid>>5, lane=tid&31;
    int wm=wid&1, wn=wid>>1;
    int t2 = blockIdx.x;
    const __nv_bfloat16* W = g_ws + (size_t)5*CH*KP2;
    const __nv_bfloat16* Ax = g_xs + (size_t)t2*64*KP2;

    float acc[2][4][4];
    #pragma unroll
    for (int mf=0;mf<2;++mf)
        #pragma unroll
        for (int nf=0;nf<4;++nf)
            #pragma unroll
            for (int r=0;r<4;++r) acc[mf][nf][r]=0.f;

    out_issue(tid, 0, 0, sb, Ax, W);
    out_issue(tid, 1, 1, sb, Ax, W);

    for (int c=0; c<NCH_P; ++c){
        if (c+1<NCH_P) cp_wait<1>(); else cp_wait<0>();
        __syncthreads();
        if (c+2<NCH_P) out_issue(tid, c+2, (c+2)%3, sb, Ax, W);
        uint32_t bofs = sb + (uint32_t)(c%3)*OSTEP3;

        uint32_t ah[2][4], al[2][4];
        #pragma unroll
        for (int mf=0; mf<2; ++mf){
            int row = wm*32 + mf*16 + (lane&15);
            int kc  = (lane>>4)*8;
            uint32_t ro = (uint32_t)(row*LDW + kc)*2;
            ldsm4(ah[mf][0],ah[mf][1],ah[mf][2],ah[mf][3], bofs + ro);
            ldsm4(al[mf][0],al[mf][1],al[mf][2],al[mf][3], bofs + 3072u + ro);
        }
        uint32_t bf[4][2];
        ldB(bofs + 6144u, wn, lane, bf);   // Wh
        #pragma unroll
        for (int mf=0; mf<2; ++mf)
            #pragma unroll
            for (int nf=0; nf<4; ++nf){
                mma16816(acc[mf][nf], ah[mf], bf[nf]);
                mma16816(acc[mf][nf], al[mf], bf[nf]);
            }
        ldB(bofs + 12288u, wn, lane, bf);  // Wl
        #pragma unroll
        for (int mf=0; mf<2; ++mf)
            #pragma unroll
            for (int nf=0; nf<4; ++nf)
                mma16816(acc[mf][nf], ah[mf], bf[nf]);
    }

    #pragma unroll
    for (int mf=0; mf<2; ++mf)
        #pragma unroll
        for (int nf=0; nf<4; ++nf){
            int col = wn*32 + nf*8 + (lane&3)*2;
            int row = wm*32 + mf*16 + (lane>>2);
            size_t R0 = (size_t)t2*64 + row;
            float2 zb2 = *(const float2*)(zb + col);
            float2 ga = *(const float2*)(g_gate + R0*CH + col);
            float2 gb2 = *(const float2*)(g_gate + (R0+8)*CH + col);
            *(float2*)(out + R0*CH + col) =
                make_float2(ga.x*(acc[mf][nf][0]+zb2.x), ga.y*(acc[mf][nf][1]+zb2.y));
            *(float2*)(out + (R0+8)*CH + col) =
                make_float2(gb2.x*(acc[mf][nf][2]+zb2.x), gb2.y*(acc[mf][nf][3]+zb2.y));
        }
}

extern "C" void kernel_launch(void* const* d_in, const int* in_sizes, int n_in,
                              void* d_out, int out_size) {
    const float* z      = (const float*)d_in[0];
    const float* mask   = (const float*)d_in[1];
    const float* ln_in_w= (const float*)d_in[2];
    const float* ln_in_b= (const float*)d_in[3];
    const float* a_g_w  = (const float*)d_in[4];
    const float* a_g_b  = (const float*)d_in[5];
    const float* a_p_w  = (const float*)d_in[6];
    const float* a_p_b  = (const float*)d_in[7];
    const float* b_g_w  = (const float*)d_in[8];
    const float* b_g_b  = (const float*)d_in[9];
    const float* b_p_w  = (const float*)d_in[10];
    const float* b_p_b  = (const float*)d_in[11];
    const float* g_w    = (const float*)d_in[12];
    const float* g_b    = (const float*)d_in[13];
    const float* ln_out_w=(const float*)d_in[14];
    const float* ln_out_b=(const float*)d_in[15];
    const float* z_w    = (const float*)d_in[16];
    const float* z_b    = (const float*)d_in[17];
    float* out = (float*)d_out;

    cudaFuncSetAttribute(projmma_kernel, cudaFuncAttributeMaxDynamicSharedMemorySize, 3*PSTEP3);
    cudaFuncSetAttribute(tri_mma_kernel, cudaFuncAttributeMaxDynamicSharedMemorySize, 3*TSTEP3);
    cudaFuncSetAttribute(outmma_kernel, cudaFuncAttributeMaxDynamicSharedMemorySize, 3*OSTEP3);

    wsplit_kernel<<<6,256>>>(a_g_w, a_p_w, b_g_w, b_p_w, g_w, z_w);
    ln_split_kernel<<<NN/8,256>>>(z, ln_in_w, ln_in_b);
    projmma_kernel<<<dim3(2304,3),256,3*PSTEP3>>>(mask, a_g_b, a_p_b, b_g_b, b_p_b, g_b);
    tri_mma_kernel<<<dim3(3,3,CH),256,3*TSTEP3>>>();
    ln_out_split_kernel<<<NN/64,256>>>(ln_out_w, ln_out_b);
    outmma_kernel<<<NN/64,256,3*OSTEP3>>>(z_b, out);
}

// round 11
// speedup vs baseline: 1.1259x; 1.1259x over previous
#include <cuda_runtime.h>
#include <cuda_bf16.h>
#include <cstdint>

#define NRES 384
#define CH 128
#define NN (NRES*NRES)
#define EPSF 1e-5f
#define KS2 768           // triangle operand row: [hi(384)|lo(384)]
#define KP2 256           // proj/out row: [hi(128)|lo(128)]
#define BK 32
#define LDW 40            // bf16 per padded smem row (80B)

// ---- scratch (device globals; no allocation) ----
__device__ __nv_bfloat16 g_as[(size_t)CH*NRES*KS2];
__device__ __nv_bfloat16 g_bs[(size_t)CH*NRES*KS2];
__device__ __nv_bfloat16 g_zs[(size_t)NN*KP2];
__device__ __nv_bfloat16 g_ws[(size_t)6*CH*KP2];
__device__ float g_gate[(size_t)NN*CH];
__device__ float g_xt[(size_t)CH*NN];

__device__ __forceinline__ float sigf(float x){ return 1.f/(1.f+__expf(-x)); }

__device__ __forceinline__ uint32_t s2u(const void* p){
    uint32_t a;
    asm("{ .reg .u64 t; cvta.to.shared.u64 t, %1; cvt.u32.u64 %0, t; }" : "=r"(a) : "l"(p));
    return a;
}
__device__ __forceinline__ void ldsm4(uint32_t &r0,uint32_t &r1,uint32_t &r2,uint32_t &r3,uint32_t a){
    asm volatile("ldmatrix.sync.aligned.m8n8.x4.shared.b16 {%0,%1,%2,%3}, [%4];"
        : "=r"(r0),"=r"(r1),"=r"(r2),"=r"(r3) : "r"(a));
}
__device__ __forceinline__ void mma16816(float* d, const uint32_t* a, const uint32_t* b){
    asm volatile("mma.sync.aligned.m16n8k16.row.col.f32.bf16.bf16.f32 "
        "{%0,%1,%2,%3}, {%4,%5,%6,%7}, {%8,%9}, {%0,%1,%2,%3};"
        : "+f"(d[0]),"+f"(d[1]),"+f"(d[2]),"+f"(d[3])
        : "r"(a[0]),"r"(a[1]),"r"(a[2]),"r"(a[3]), "r"(b[0]),"r"(b[1]));
}
__device__ __forceinline__ void cpa(uint32_t d, const void* s){
    asm volatile("cp.async.ca.shared.global [%0], [%1], 16;" :: "r"(d), "l"(s) : "memory");
}
__device__ __forceinline__ void cp_commit(){ asm volatile("cp.async.commit_group;" ::: "memory"); }
template<int N> __device__ __forceinline__ void cp_wait(){ asm volatile("cp.async.wait_group %0;" :: "n"(N) : "memory"); }

// B fragments: 4 n8k16 tiles (32 n-rows) from padded smem (LDW bf16/row)
__device__ __forceinline__ void ldB(uint32_t base, int wn, int lane, int ks, uint32_t bf[4][2]){
    int kc = ks*16 + ((lane>>3)&1)*8;
    #pragma unroll
    for (int nf2=0; nf2<2; ++nf2){
        int nrow = wn*32 + nf2*16 + (lane&7) + ((lane>>4)<<3);
        uint32_t r0,r1,r2,r3;
        ldsm4(r0,r1,r2,r3, base + (uint32_t)(nrow*LDW + kc)*2);
        bf[nf2*2+0][0]=r0; bf[nf2*2+0][1]=r1;
        bf[nf2*2+1][0]=r2; bf[nf2*2+1][1]=r3;
    }
}

// ---- split 6 weights into bf16 [Wh|Wl] ----
__global__ void wsplit_kernel(const float* w0, const float* w1, const float* w2,
                              const float* w3, const float* w4, const float* w5){
    const float* srcs[6] = {w0,w1,w2,w3,w4,w5};
    const float* W = srcs[blockIdx.x];
    __nv_bfloat16* dst = g_ws + (size_t)blockIdx.x*CH*KP2;
    for (int it=0; it<64; ++it){
        int idx = threadIdx.x + it*256;
        int o = idx>>7, k = idx&127;
        float v = W[idx];
        __nv_bfloat16 hi = __float2bfloat16(v);
        __nv_bfloat16 lo = __float2bfloat16(v - __bfloat162float(hi));
        dst[(size_t)o*KP2 + k]       = hi;
        dst[(size_t)o*KP2 + 128 + k] = lo;
    }
}

// ---- LN(z) -> split bf16 rows [zh|zl] ----
__global__ __launch_bounds__(256)
void ln_split_kernel(const float* __restrict__ z,
                     const float* __restrict__ lnw, const float* __restrict__ lnb){
    int tid=threadIdx.x, wid=tid>>5, lane=tid&31;
    size_t row = (size_t)blockIdx.x*8 + wid;
    float4 v = *(const float4*)(z + row*CH + lane*4);
    float s = v.x+v.y+v.z+v.w;
    float q = v.x*v.x+v.y*v.y+v.z*v.z+v.w*v.w;
    #pragma unroll
    for (int o=16;o>0;o>>=1){ s+=__shfl_xor_sync(0xffffffffu,s,o); q+=__shfl_xor_sync(0xffffffffu,q,o); }
    float mu=s*(1.f/128.f), var=q*(1.f/128.f)-mu*mu;
    float rs=rsqrtf(fmaxf(var,0.f)+EPSF);
    float4 w4 = *(const float4*)(lnw + lane*4);
    float4 b4 = *(const float4*)(lnb + lane*4);
    float n[4] = {(v.x-mu)*rs*w4.x+b4.x, (v.y-mu)*rs*w4.y+b4.y,
                  (v.z-mu)*rs*w4.z+b4.z, (v.w-mu)*rs*w4.w+b4.w};
    __nv_bfloat16 hi[4], lo[4];
    #pragma unroll
    for (int j=0;j<4;++j){
        hi[j] = __float2bfloat16(n[j]);
        lo[j] = __float2bfloat16(n[j]-__bfloat162float(hi[j]));
    }
    __nv_bfloat16* d = g_zs + row*KP2 + lane*4;
    *(__nv_bfloat162*)(d)     = __nv_bfloat162{hi[0],hi[1]};
    *(__nv_bfloat162*)(d+2)   = __nv_bfloat162{hi[2],hi[3]};
    *(__nv_bfloat162*)(d+128) = __nv_bfloat162{lo[0],lo[1]};
    *(__nv_bfloat162*)(d+130) = __nv_bfloat162{lo[2],lo[3]};
}

// ================= projmma (R9 form): 64-row tiles, grid (2304,3) =================
// stage regions: Zh 0, Zl 5120, Gh 10240, Gl 20480, Ph 30720, Pl 40960
#define PSTEP 51200u
#define NCH_P 4

__device__ __forceinline__ void proj_issue(int tid, int c, int buf, bool hasP,
    uint32_t sb, const __nv_bfloat16* Az, const __nv_bfloat16* WG, const __nv_bfloat16* WP){
    uint32_t bofs = (uint32_t)buf*PSTEP;
    {
        int row = tid>>2, seg = tid&3;
        uint32_t off = bofs + (uint32_t)(row*80 + seg*16);
        const __nv_bfloat16* ar = Az + (size_t)row*KP2 + c*BK + seg*8;
        cpa(sb + off, ar);            // zh
        cpa(sb + 5120u + off, ar+128);// zl
    }
    #pragma unroll
    for (int it=0; it<2; ++it){
        int idx = tid + it*256;
        int row = idx>>2, seg = idx&3;
        uint32_t off = bofs + (uint32_t)(row*80 + seg*16);
        const __nv_bfloat16* gr = WG + (size_t)row*KP2 + c*BK + seg*8;
        cpa(sb + 10240u + off, gr);
        cpa(sb + 20480u + off, gr+128);
        if (hasP){
            const __nv_bfloat16* pr = WP + (size_t)row*KP2 + c*BK + seg*8;
            cpa(sb + 30720u + off, pr);
            cpa(sb + 40960u + off, pr+128);
        }
    }
    cp_commit();
}

__global__ __launch_bounds__(256,2)
void projmma_kernel(const float* __restrict__ mask_,
                    const float* __restrict__ agb, const float* __restrict__ apb,
                    const float* __restrict__ bgb, const float* __restrict__ bpb,
                    const float* __restrict__ gb_)
{
    extern __shared__ char sm[];
    uint32_t sb = s2u(sm);
    float* ot = (float*)sm;

    int tid=threadIdx.x, wid=tid>>5, lane=tid&31;
    int wm=wid&1, wn=wid>>1;
    int t2 = blockIdx.x, ph = blockIdx.y;
    bool hasP = ph<2;
    const __nv_bfloat16* WG = g_ws + (size_t)(hasP ? 2*ph : 4)*CH*KP2;
    const __nv_bfloat16* WP = g_ws + (size_t)(hasP ? 2*ph+1 : 4)*CH*KP2;
    const float* GBp = (ph==0)?agb:((ph==1)?bgb:gb_);
    const float* PBp = (ph==0)?apb:bpb;
    const __nv_bfloat16* Az = g_zs + (size_t)t2*64*KP2;

    float accG[2][4][4], accP[2][4][4];
    #pragma unroll
    for (int mf=0;mf<2;++mf)
        #pragma unroll
        for (int nf=0;nf<4;++nf)
            #pragma unroll
            for (int r=0;r<4;++r){ accG[mf][nf][r]=0.f; accP[mf][nf][r]=0.f; }

    proj_issue(tid, 0, 0, hasP, sb, Az, WG, WP);

    for (int c=0; c<NCH_P; ++c){
        int buf = c & 1;
        if (c+1<NCH_P){ proj_issue(tid, c+1, buf^1, hasP, sb, Az, WG, WP); cp_wait<1>(); }
        else cp_wait<0>();
        __syncthreads();
        uint32_t bofs = sb + (uint32_t)buf*PSTEP;
        #pragma unroll
        for (int ks=0; ks<2; ++ks){
            uint32_t ah[2][4], al[2][4];
            #pragma unroll
            for (int mf=0; mf<2; ++mf){
                int row = wm*32 + mf*16 + (lane&15);
                int kc  = ks*16 + (lane>>4)*8;
                uint32_t ro = (uint32_t)(row*LDW + kc)*2;
                ldsm4(ah[mf][0],ah[mf][1],ah[mf][2],ah[mf][3], bofs + ro);
                ldsm4(al[mf][0],al[mf][1],al[mf][2],al[mf][3], bofs + 5120u + ro);
            }
            uint32_t bf[4][2];
            ldB(bofs + 10240u, wn, lane, ks, bf);   // Gh
            #pragma unroll
            for (int mf=0; mf<2; ++mf)
                #pragma unroll
                for (int nf=0; nf<4; ++nf){
                    mma16816(accG[mf][nf], ah[mf], bf[nf]);
                    mma16816(accG[mf][nf], al[mf], bf[nf]);
                }
            ldB(bofs + 20480u, wn, lane, ks, bf);   // Gl
            #pragma unroll
            for (int mf=0; mf<2; ++mf)
                #pragma unroll
                for (int nf=0; nf<4; ++nf)
                    mma16816(accG[mf][nf], ah[mf], bf[nf]);
            if (hasP){
                ldB(bofs + 30720u, wn, lane, ks, bf);  // Ph
                #pragma unroll
                for (int mf=0; mf<2; ++mf)
                    #pragma unroll
                    for (int nf=0; nf<4; ++nf){
                        mma16816(accP[mf][nf], ah[mf], bf[nf]);
                        mma16816(accP[mf][nf], al[mf], bf[nf]);
                    }
                ldB(bofs + 40960u, wn, lane, ks, bf);  // Pl
                #pragma unroll
                for (int mf=0; mf<2; ++mf)
                    #pragma unroll
                    for (int nf=0; nf<4; ++nf)
                        mma16816(accP[mf][nf], ah[mf], bf[nf]);
            }
        }
        __syncthreads();
    }

    if (hasP){
        __nv_bfloat16* dst = ph ? g_bs : g_as;
        int i_idx = t2/6, k0 = (t2%6)*64;
        #pragma unroll
        for (int mf=0; mf<2; ++mf)
            #pragma unroll
            for (int nf=0; nf<4; ++nf){
                int col = wn*32 + nf*8 + (lane&3)*2;
                int row = wm*32 + mf*16 + (lane>>2);
                float mk0 = __ldg(mask_ + t2*64 + row);
                float mk1 = __ldg(mask_ + t2*64 + row + 8);
                float g0=__ldg(GBp+col), g1=__ldg(GBp+col+1);
                float p0=__ldg(PBp+col), p1=__ldg(PBp+col+1);
                ot[col*68+row]       = mk0*sigf(accG[mf][nf][0]+g0)*(accP[mf][nf][0]+p0);
                ot[(col+1)*68+row]   = mk0*sigf(accG[mf][nf][1]+g1)*(accP[mf][nf][1]+p1);
                ot[col*68+row+8]     = mk1*sigf(accG[mf][nf][2]+g0)*(accP[mf][nf][2]+p0);
                ot[(col+1)*68+row+8] = mk1*sigf(accG[mf][nf][3]+g1)*(accP[mf][nf][3]+p1);
            }
        __syncthreads();
        #pragma unroll
        for (int it2=0; it2<32; ++it2){
            int f = tid + it2*256;
            int r = f&63, o = f>>6;
            float v = ot[o*68 + r];
            __nv_bfloat16 hi = __float2bfloat16(v);
            __nv_bfloat16 lo = __float2bfloat16(v - __bfloat162float(hi));
            size_t base = (size_t)o*(NRES*KS2) + (size_t)i_idx*KS2 + (k0 + r);
            dst[base]       = hi;
            dst[base + 384] = lo;
        }
    } else {
        #pragma unroll
        for (int mf=0; mf<2; ++mf)
            #pragma unroll
            for (int nf=0; nf<4; ++nf){
                int col = wn*32 + nf*8 + (lane&3)*2;
                int row = wm*32 + mf*16 + (lane>>2);
                size_t R0 = (size_t)t2*64 + row;
                float g0=__ldg(GBp+col), g1=__ldg(GBp+col+1);
                *(float2*)(g_gate + R0*CH + col) =
                    make_float2(sigf(accG[mf][nf][0]+g0), sigf(accG[mf][nf][1]+g1));
                *(float2*)(g_gate + (R0+8)*CH + col) =
                    make_float2(sigf(accG[mf][nf][2]+g0), sigf(accG[mf][nf][3]+g1));
            }
    }
}

// ================= tri (R9 form): per (h,i-tile,j-tile), 2-stage BK=32 =================
// stage regions: Ah 0, Al 10240, Bh 20480, Bl 30720
#define TSTEP 40960u
#define NCH_T 12

__device__ __forceinline__ void tri_issue(int tid, int c, int buf,
    const __nv_bfloat16* Ag, const __nv_bfloat16* Bg, uint32_t sb){
    int row2 = tid>>2, seg = tid&3;
    uint32_t bofs = (uint32_t)buf*TSTEP;
    #pragma unroll
    for (int it=0; it<2; ++it){
        int row = row2 + it*64;
        uint32_t off = bofs + (uint32_t)(row*80 + seg*16);
        const __nv_bfloat16* ar = Ag + (size_t)row*KS2 + c*BK + seg*8;
        cpa(sb + off,           ar);
        cpa(sb + 10240u + off,  ar+384);
        const __nv_bfloat16* br = Bg + (size_t)row*KS2 + c*BK + seg*8;
        cpa(sb + 20480u + off,  br);
        cpa(sb + 30720u + off,  br+384);
    }
    cp_commit();
}

__global__ __launch_bounds__(256,2)
void tri_mma_kernel(){
    extern __shared__ char sm[];
    uint32_t sb = s2u(sm);

    int tid = threadIdx.x;
    int wid = tid>>5, lane = tid&31;
    int wm = wid & 1, wn = wid >> 1;
    int h = blockIdx.z, i0 = blockIdx.y*128, j0 = blockIdx.x*128;

    const __nv_bfloat16* Ag = g_as + ((size_t)h*NRES + i0)*KS2;
    const __nv_bfloat16* Bg = g_bs + ((size_t)h*NRES + j0)*KS2;

    float acc[4][4][4];
    #pragma unroll
    for (int mf=0;mf<4;++mf)
        #pragma unroll
        for (int nf=0;nf<4;++nf)
            #pragma unroll
            for (int r=0;r<4;++r) acc[mf][nf][r]=0.f;

    tri_issue(tid, 0, 0, Ag, Bg, sb);

    for (int c=0; c<NCH_T; ++c){
        int buf = c & 1;
        if (c+1 < NCH_T){ tri_issue(tid, c+1, buf^1, Ag, Bg, sb); cp_wait<1>(); }
        else cp_wait<0>();
        __syncthreads();
        uint32_t bofs = sb + (uint32_t)buf*TSTEP;
        #pragma unroll
        for (int ks=0; ks<2; ++ks){
            uint32_t ah[4][4];
            #pragma unroll
            for (int mf=0; mf<4; ++mf){
                int row = wm*64 + mf*16 + (lane&15);
                int kc  = ks*16 + (lane>>4)*8;
                ldsm4(ah[mf][0],ah[mf][1],ah[mf][2],ah[mf][3], bofs + (uint32_t)(row*LDW + kc)*2);
            }
            uint32_t bh[4][2];
            ldB(bofs + 20480u, wn, lane, ks, bh);   // Bh
            #pragma unroll
            for (int mf=0; mf<4; ++mf)
                #pragma unroll
                for (int nf=0; nf<4; ++nf)
                    mma16816(acc[mf][nf], ah[mf], bh[nf]);
            {
                uint32_t bl[4][2];
                ldB(bofs + 30720u, wn, lane, ks, bl);  // Bl
                #pragma unroll
                for (int mf=0; mf<4; ++mf)
                    #pragma unroll
                    for (int nf=0; nf<4; ++nf)
                        mma16816(acc[mf][nf], ah[mf], bl[nf]);
            }
            #pragma unroll
            for (int mf=0; mf<4; ++mf){   // reuse ah regs for Al
                int row = wm*64 + mf*16 + (lane&15);
                int kc  = ks*16 + (lane>>4)*8;
                ldsm4(ah[mf][0],ah[mf][1],ah[mf][2],ah[mf][3], bofs + 10240u + (uint32_t)(row*LDW + kc)*2);
            }
            #pragma unroll
            for (int mf=0; mf<4; ++mf)
                #pragma unroll
                for (int nf=0; nf<4; ++nf)
                    mma16816(acc[mf][nf], ah[mf], bh[nf]);
        }
        __syncthreads();
    }

    float* X = g_xt + (size_t)h*NN;
    #pragma unroll
    for (int mf=0; mf<4; ++mf){
        #pragma unroll
        for (int nf=0; nf<4; ++nf){
            int row = i0 + wm*64 + mf*16 + (lane>>2);
            int col = j0 + wn*32 + nf*8 + (lane&3)*2;
            *(float2*)(X + (size_t)row*NRES + col)     = make_float2(acc[mf][nf][0], acc[mf][nf][1]);
            *(float2*)(X + (size_t)(row+8)*NRES + col) = make_float2(acc[mf][nf][2], acc[mf][nf][3]);
        }
    }
}

// ================= outmma (FUSED LN): out = gate * (LN(x) @ z_w^T + z_b) =================
// smem: A-full [0,40960): chunk c at c*10240 (Xh), +5120 (Xl); W db at 40960 + buf*20480
// xs prologue scratch (128x66 fp32 = 33792B) overlaps W region at 40960.
#define OA_FULL 40960u
#define OWSTEP 20480u

__device__ __forceinline__ void outw_issue(int tid, int c, int buf, uint32_t sb,
                                           const __nv_bfloat16* W){
    uint32_t bofs = OA_FULL + (uint32_t)buf*OWSTEP;
    #pragma unroll
    for (int it=0; it<2; ++it){
        int idx = tid + it*256;
        int row = idx>>2, seg = idx&3;
        uint32_t off = bofs + (uint32_t)(row*80 + seg*16);
        const __nv_bfloat16* wr = W + (size_t)row*KP2 + c*BK + seg*8;
        cpa(sb + off,          wr);
        cpa(sb + 10240u + off, wr+128);
    }
    cp_commit();
}

__global__ __launch_bounds__(256,2)
void outmma_kernel(const float* __restrict__ low, const float* __restrict__ lob,
                   const float* __restrict__ zb, float* __restrict__ out)
{
    extern __shared__ char sm[];
    uint32_t sb = s2u(sm);
    float* xs = (float*)(sm + OA_FULL);   // scratch, freed before W loads
    __shared__ float mu_s[64], rs_s[64], low_s[128], lob_s[128];

    int tid=threadIdx.x, wid=tid>>5, lane=tid&31;
    int wm=wid&1, wn=wid>>1;
    int t2 = blockIdx.x;
    int row0 = t2*64;

    if (tid<128){ low_s[tid]=low[tid]; lob_s[tid]=lob[tid]; }
    // load x tile [h][r] (transposed gather, coalesced over r)
    #pragma unroll
    for (int it=0; it<32; ++it){
        int f = tid + it*256;
        int r = f&63, h = f>>6;
        xs[h*66 + r] = g_xt[(size_t)h*NN + row0 + r];
    }
    __syncthreads();
    // LN stats over h per row
    #pragma unroll
    for (int rr=0;rr<8;++rr){
        int r = wid*8+rr;
        float s=0.f,q=0.f;
        #pragma unroll
        for (int m=0;m<4;++m){ float x=xs[(lane+32*m)*66 + r]; s+=x; q+=x*x; }
        #pragma unroll
        for (int o=16;o>0;o>>=1){ s+=__shfl_xor_sync(0xffffffffu,s,o); q+=__shfl_xor_sync(0xffffffffu,q,o); }
        if (lane==0){
            float mu=s*(1.f/128.f), var=q*(1.f/128.f)-mu*mu;
            mu_s[r]=mu; rs_s[r]=rsqrtf(fmaxf(var,0.f)+EPSF);
        }
    }
    __syncthreads();
    // normalize + split -> A-full region (padded 80B rows, k within chunk)
    #pragma unroll
    for (int it=0; it<16; ++it){
        int f = tid + it*256;
        int r = f>>6, h2 = (f&63)*2;
        float mu=mu_s[r], rs=rs_s[r];
        float x0 = (xs[(h2+0)*66+r]-mu)*rs*low_s[h2+0]+lob_s[h2+0];
        float x1 = (xs[(h2+1)*66+r]-mu)*rs*low_s[h2+1]+lob_s[h2+1];
        __nv_bfloat16 h0=__float2bfloat16(x0), h1=__float2bfloat16(x1);
        __nv_bfloat16 l0=__float2bfloat16(x0-__bfloat162float(h0));
        __nv_bfloat16 l1=__float2bfloat16(x1-__bfloat162float(h1));
        uint32_t off = (uint32_t)(h2>>5)*10240u + (uint32_t)(r*80 + (h2&31)*2);
        *(__nv_bfloat162*)(sm + off)          = __nv_bfloat162{h0,h1};
        *(__nv_bfloat162*)(sm + off + 5120u)  = __nv_bfloat162{l0,l1};
    }
    __syncthreads();   // A-full ready; xs region now free for W streaming

    const __nv_bfloat16* W = g_ws + (size_t)5*CH*KP2;
    float acc[2][4][4];
    #pragma unroll
    for (int mf=0;mf<2;++mf)
        #pragma unroll
        for (int nf=0;nf<4;++nf)
            #pragma unroll
            for (int r=0;r<4;++r) acc[mf][nf][r]=0.f;

    outw_issue(tid, 0, 0, sb, W);

    for (int c=0; c<NCH_P; ++c){
        int buf = c & 1;
        if (c+1<NCH_P){ outw_issue(tid, c+1, buf^1, sb, W); cp_wait<1>(); }
        else cp_wait<0>();
        __syncthreads();
        uint32_t abase = sb + (uint32_t)c*10240u;
        uint32_t wbase = sb + OA_FULL + (uint32_t)buf*OWSTEP;
        #pragma unroll
        for (int ks=0; ks<2; ++ks){
            uint32_t ah[2][4], al[2][4];
            #pragma unroll
            for (int mf=0; mf<2; ++mf){
                int row = wm*32 + mf*16 + (lane&15);
                int kc  = ks*16 + (lane>>4)*8;
                uint32_t ro = (uint32_t)(row*LDW + kc)*2;
                ldsm4(ah[mf][0],ah[mf][1],ah[mf][2],ah[mf][3], abase + ro);
                ldsm4(al[mf][0],al[mf][1],al[mf][2],al[mf][3], abase + 5120u + ro);
            }
            uint32_t bf[4][2];
            ldB(wbase, wn, lane, ks, bf);            // Wh
            #pragma unroll
            for (int mf=0; mf<2; ++mf)
                #pragma unroll
                for (int nf=0; nf<4; ++nf){
                    mma16816(acc[mf][nf], ah[mf], bf[nf]);
                    mma16816(acc[mf][nf], al[mf], bf[nf]);
                }
            ldB(wbase + 10240u, wn, lane, ks, bf);   // Wl
            #pragma unroll
            for (int mf=0; mf<2; ++mf)
                #pragma unroll
                for (int nf=0; nf<4; ++nf)
                    mma16816(acc[mf][nf], ah[mf], bf[nf]);
        }
        __syncthreads();
    }

    #pragma unroll
    for (int mf=0; mf<2; ++mf)
        #pragma unroll
        for (int nf=0; nf<4; ++nf){
            int col = wn*32 + nf*8 + (lane&3)*2;
            int row = wm*32 + mf*16 + (lane>>2);
            size_t R0 = (size_t)row0 + row;
            float2 zb2 = *(const float2*)(zb + col);
            float2 ga = *(const float2*)(g_gate + R0*CH + col);
            float2 gb2 = *(const float2*)(g_gate + (R0+8)*CH + col);
            *(float2*)(out + R0*CH + col) =
                make_float2(ga.x*(acc[mf][nf][0]+zb2.x), ga.y*(acc[mf][nf][1]+zb2.y));
            *(float2*)(out + (R0+8)*CH + col) =
                make_float2(gb2.x*(acc[mf][nf][2]+zb2.x), gb2.y*(acc[mf][nf][3]+zb2.y));
        }
}

extern "C" void kernel_launch(void* const* d_in, const int* in_sizes, int n_in,
                              void* d_out, int out_size) {
    const float* z      = (const float*)d_in[0];
    const float* mask   = (const float*)d_in[1];
    const float* ln_in_w= (const float*)d_in[2];
    const float* ln_in_b= (const float*)d_in[3];
    const float* a_g_w  = (const float*)d_in[4];
    const float* a_g_b  = (const float*)d_in[5];
    const float* a_p_w  = (const float*)d_in[6];
    const float* a_p_b  = (const float*)d_in[7];
    const float* b_g_w  = (const float*)d_in[8];
    const float* b_g_b  = (const float*)d_in[9];
    const float* b_p_w  = (const float*)d_in[10];
    const float* b_p_b  = (const float*)d_in[11];
    const float* g_w    = (const float*)d_in[12];
    const float* g_b    = (const float*)d_in[13];
    const float* ln_out_w=(const float*)d_in[14];
    const float* ln_out_b=(const float*)d_in[15];
    const float* z_w    = (const float*)d_in[16];
    const float* z_b    = (const float*)d_in[17];
    float* out = (float*)d_out;

    cudaFuncSetAttribute(projmma_kernel, cudaFuncAttributeMaxDynamicSharedMemorySize, 2*PSTEP);
    cudaFuncSetAttribute(tri_mma_kernel, cudaFuncAttributeMaxDynamicSharedMemorySize, 2*TSTEP);
    cudaFuncSetAttribute(outmma_kernel, cudaFuncAttributeMaxDynamicSharedMemorySize, 81920);

    wsplit_kernel<<<6,256>>>(a_g_w, a_p_w, b_g_w, b_p_w, g_w, z_w);
    ln_split_kernel<<<NN/8,256>>>(z, ln_in_w, ln_in_b);
    projmma_kernel<<<dim3(2304,3),256,2*PSTEP>>>(mask, a_g_b, a_p_b, b_g_b, b_p_b, g_b);
    tri_mma_kernel<<<dim3(3,3,CH),256,2*TSTEP>>>();
    outmma_kernel<<<NN/64,256,81920>>>(ln_out_w, ln_out_b, z_b, out);
}

// round 12
// speedup vs baseline: 1.1446x; 1.0167x over previous
#include <cuda_runtime.h>
#include <cuda_bf16.h>
#include <cstdint>

#define NRES 384
#define CH 128
#define NN (NRES*NRES)
#define EPSF 1e-5f
#define KS2 768           // triangle operand row: [hi(384)|lo(384)]
#define KP2 256           // proj/out row: [hi(128)|lo(128)]
#define BK 32
#define LDW 40            // bf16 per padded smem row (80B)

// ---- scratch (device globals; no allocation) ----
__device__ __nv_bfloat16 g_as[(size_t)CH*NRES*KS2];
__device__ __nv_bfloat16 g_bs[(size_t)CH*NRES*KS2];
__device__ __nv_bfloat16 g_zs[(size_t)NN*KP2];
__device__ __nv_bfloat16 g_ws[(size_t)6*CH*KP2];
__device__ float g_gate[(size_t)NN*CH];
__device__ float g_xt[(size_t)CH*NN];

__device__ __forceinline__ float sigf(float x){ return 1.f/(1.f+__expf(-x)); }

__device__ __forceinline__ uint32_t s2u(const void* p){
    uint32_t a;
    asm("{ .reg .u64 t; cvta.to.shared.u64 t, %1; cvt.u32.u64 %0, t; }" : "=r"(a) : "l"(p));
    return a;
}
__device__ __forceinline__ void ldsm4(uint32_t &r0,uint32_t &r1,uint32_t &r2,uint32_t &r3,uint32_t a){
    asm volatile("ldmatrix.sync.aligned.m8n8.x4.shared.b16 {%0,%1,%2,%3}, [%4];"
        : "=r"(r0),"=r"(r1),"=r"(r2),"=r"(r3) : "r"(a));
}
__device__ __forceinline__ void mma16816(float* d, const uint32_t* a, const uint32_t* b){
    asm volatile("mma.sync.aligned.m16n8k16.row.col.f32.bf16.bf16.f32 "
        "{%0,%1,%2,%3}, {%4,%5,%6,%7}, {%8,%9}, {%0,%1,%2,%3};"
        : "+f"(d[0]),"+f"(d[1]),"+f"(d[2]),"+f"(d[3])
        : "r"(a[0]),"r"(a[1]),"r"(a[2]),"r"(a[3]), "r"(b[0]),"r"(b[1]));
}
__device__ __forceinline__ void cpa(uint32_t d, const void* s){
    asm volatile("cp.async.ca.shared.global [%0], [%1], 16;" :: "r"(d), "l"(s) : "memory");
}
__device__ __forceinline__ void cp_commit(){ asm volatile("cp.async.commit_group;" ::: "memory"); }
template<int N> __device__ __forceinline__ void cp_wait(){ asm volatile("cp.async.wait_group %0;" :: "n"(N) : "memory"); }

// B fragments: 4 n8k16 tiles (32 n-rows) from padded smem (LDW bf16/row)
__device__ __forceinline__ void ldB(uint32_t base, int wn, int lane, int ks, uint32_t bf[4][2]){
    int kc = ks*16 + ((lane>>3)&1)*8;
    #pragma unroll
    for (int nf2=0; nf2<2; ++nf2){
        int nrow = wn*32 + nf2*16 + (lane&7) + ((lane>>4)<<3);
        uint32_t r0,r1,r2,r3;
        ldsm4(r0,r1,r2,r3, base + (uint32_t)(nrow*LDW + kc)*2);
        bf[nf2*2+0][0]=r0; bf[nf2*2+0][1]=r1;
        bf[nf2*2+1][0]=r2; bf[nf2*2+1][1]=r3;
    }
}

// ---- split 6 weights into bf16 [Wh|Wl] ----
__global__ void wsplit_kernel(const float* w0, const float* w1, const float* w2,
                              const float* w3, const float* w4, const float* w5){
    const float* srcs[6] = {w0,w1,w2,w3,w4,w5};
    const float* W = srcs[blockIdx.x];
    __nv_bfloat16* dst = g_ws + (size_t)blockIdx.x*CH*KP2;
    for (int it=0; it<64; ++it){
        int idx = threadIdx.x + it*256;
        int o = idx>>7, k = idx&127;
        float v = W[idx];
        __nv_bfloat16 hi = __float2bfloat16(v);
        __nv_bfloat16 lo = __float2bfloat16(v - __bfloat162float(hi));
        dst[(size_t)o*KP2 + k]       = hi;
        dst[(size_t)o*KP2 + 128 + k] = lo;
    }
}

// ---- LN(z) -> split bf16 rows [zh|zl] ----
__global__ __launch_bounds__(256)
void ln_split_kernel(const float* __restrict__ z,
                     const float* __restrict__ lnw, const float* __restrict__ lnb){
    int tid=threadIdx.x, wid=tid>>5, lane=tid&31;
    size_t row = (size_t)blockIdx.x*8 + wid;
    float4 v = *(const float4*)(z + row*CH + lane*4);
    float s = v.x+v.y+v.z+v.w;
    float q = v.x*v.x+v.y*v.y+v.z*v.z+v.w*v.w;
    #pragma unroll
    for (int o=16;o>0;o>>=1){ s+=__shfl_xor_sync(0xffffffffu,s,o); q+=__shfl_xor_sync(0xffffffffu,q,o); }
    float mu=s*(1.f/128.f), var=q*(1.f/128.f)-mu*mu;
    float rs=rsqrtf(fmaxf(var,0.f)+EPSF);
    float4 w4 = *(const float4*)(lnw + lane*4);
    float4 b4 = *(const float4*)(lnb + lane*4);
    float n[4] = {(v.x-mu)*rs*w4.x+b4.x, (v.y-mu)*rs*w4.y+b4.y,
                  (v.z-mu)*rs*w4.z+b4.z, (v.w-mu)*rs*w4.w+b4.w};
    __nv_bfloat16 hi[4], lo[4];
    #pragma unroll
    for (int j=0;j<4;++j){
        hi[j] = __float2bfloat16(n[j]);
        lo[j] = __float2bfloat16(n[j]-__bfloat162float(hi[j]));
    }
    __nv_bfloat16* d = g_zs + row*KP2 + lane*4;
    *(__nv_bfloat162*)(d)     = __nv_bfloat162{hi[0],hi[1]};
    *(__nv_bfloat162*)(d+2)   = __nv_bfloat162{hi[2],hi[3]};
    *(__nv_bfloat162*)(d+128) = __nv_bfloat162{lo[0],lo[1]};
    *(__nv_bfloat162*)(d+130) = __nv_bfloat162{lo[2],lo[3]};
}

// ================= projmma: 64-row tiles, grid (3, 2304) — phase FASTEST =================
// stage regions: Zh 0, Zl 5120, Gh 10240, Gl 20480, Ph 30720, Pl 40960
#define PSTEP 51200u
#define NCH_P 4

__device__ __forceinline__ void proj_issue(int tid, int c, int buf, bool hasP,
    uint32_t sb, const __nv_bfloat16* Az, const __nv_bfloat16* WG, const __nv_bfloat16* WP){
    uint32_t bofs = (uint32_t)buf*PSTEP;
    {
        int row = tid>>2, seg = tid&3;
        uint32_t off = bofs + (uint32_t)(row*80 + seg*16);
        const __nv_bfloat16* ar = Az + (size_t)row*KP2 + c*BK + seg*8;
        cpa(sb + off, ar);            // zh
        cpa(sb + 5120u + off, ar+128);// zl
    }
    #pragma unroll
    for (int it=0; it<2; ++it){
        int idx = tid + it*256;
        int row = idx>>2, seg = idx&3;
        uint32_t off = bofs + (uint32_t)(row*80 + seg*16);
        const __nv_bfloat16* gr = WG + (size_t)row*KP2 + c*BK + seg*8;
        cpa(sb + 10240u + off, gr);
        cpa(sb + 20480u + off, gr+128);
        if (hasP){
            const __nv_bfloat16* pr = WP + (size_t)row*KP2 + c*BK + seg*8;
            cpa(sb + 30720u + off, pr);
            cpa(sb + 40960u + off, pr+128);
        }
    }
    cp_commit();
}

__global__ __launch_bounds__(256,2)
void projmma_kernel(const float* __restrict__ mask_,
                    const float* __restrict__ agb, const float* __restrict__ apb,
                    const float* __restrict__ bgb, const float* __restrict__ bpb,
                    const float* __restrict__ gb_)
{
    extern __shared__ char sm[];
    uint32_t sb = s2u(sm);
    float* ot = (float*)sm;

    int tid=threadIdx.x, wid=tid>>5, lane=tid&31;
    int wm=wid&1, wn=wid>>1;
    int ph = blockIdx.x, t2 = blockIdx.y;   // phase fastest: 3 phases of one tile share L2
    bool hasP = ph<2;
    const __nv_bfloat16* WG = g_ws + (size_t)(hasP ? 2*ph : 4)*CH*KP2;
    const __nv_bfloat16* WP = g_ws + (size_t)(hasP ? 2*ph+1 : 4)*CH*KP2;
    const float* GBp = (ph==0)?agb:((ph==1)?bgb:gb_);
    const float* PBp = (ph==0)?apb:bpb;
    const __nv_bfloat16* Az = g_zs + (size_t)t2*64*KP2;

    float accG[2][4][4], accP[2][4][4];
    #pragma unroll
    for (int mf=0;mf<2;++mf)
        #pragma unroll
        for (int nf=0;nf<4;++nf)
            #pragma unroll
            for (int r=0;r<4;++r){ accG[mf][nf][r]=0.f; accP[mf][nf][r]=0.f; }

    proj_issue(tid, 0, 0, hasP, sb, Az, WG, WP);

    for (int c=0; c<NCH_P; ++c){
        int buf = c & 1;
        if (c+1<NCH_P){ proj_issue(tid, c+1, buf^1, hasP, sb, Az, WG, WP); cp_wait<1>(); }
        else cp_wait<0>();
        __syncthreads();
        uint32_t bofs = sb + (uint32_t)buf*PSTEP;
        #pragma unroll
        for (int ks=0; ks<2; ++ks){
            uint32_t ah[2][4], al[2][4];
            #pragma unroll
            for (int mf=0; mf<2; ++mf){
                int row = wm*32 + mf*16 + (lane&15);
                int kc  = ks*16 + (lane>>4)*8;
                uint32_t ro = (uint32_t)(row*LDW + kc)*2;
                ldsm4(ah[mf][0],ah[mf][1],ah[mf][2],ah[mf][3], bofs + ro);
                ldsm4(al[mf][0],al[mf][1],al[mf][2],al[mf][3], bofs + 5120u + ro);
            }
            uint32_t bf[4][2];
            ldB(bofs + 10240u, wn, lane, ks, bf);   // Gh
            #pragma unroll
            for (int mf=0; mf<2; ++mf)
                #pragma unroll
                for (int nf=0; nf<4; ++nf){
                    mma16816(accG[mf][nf], ah[mf], bf[nf]);
                    mma16816(accG[mf][nf], al[mf], bf[nf]);
                }
            ldB(bofs + 20480u, wn, lane, ks, bf);   // Gl
            #pragma unroll
            for (int mf=0; mf<2; ++mf)
                #pragma unroll
                for (int nf=0; nf<4; ++nf)
                    mma16816(accG[mf][nf], ah[mf], bf[nf]);
            if (hasP){
                ldB(bofs + 30720u, wn, lane, ks, bf);  // Ph
                #pragma unroll
                for (int mf=0; mf<2; ++mf)
                    #pragma unroll
                    for (int nf=0; nf<4; ++nf){
                        mma16816(accP[mf][nf], ah[mf], bf[nf]);
                        mma16816(accP[mf][nf], al[mf], bf[nf]);
                    }
                ldB(bofs + 40960u, wn, lane, ks, bf);  // Pl
                #pragma unroll
                for (int mf=0; mf<2; ++mf)
                    #pragma unroll
                    for (int nf=0; nf<4; ++nf)
                        mma16816(accP[mf][nf], ah[mf], bf[nf]);
            }
        }
        __syncthreads();
    }

    if (hasP){
        __nv_bfloat16* dst = ph ? g_bs : g_as;
        int i_idx = t2/6, k0 = (t2%6)*64;
        #pragma unroll
        for (int mf=0; mf<2; ++mf)
            #pragma unroll
            for (int nf=0; nf<4; ++nf){
                int col = wn*32 + nf*8 + (lane&3)*2;
                int row = wm*32 + mf*16 + (lane>>2);
                float mk0 = __ldg(mask_ + t2*64 + row);
                float mk1 = __ldg(mask_ + t2*64 + row + 8);
                float g0=__ldg(GBp+col), g1=__ldg(GBp+col+1);
                float p0=__ldg(PBp+col), p1=__ldg(PBp+col+1);
                ot[col*68+row]       = mk0*sigf(accG[mf][nf][0]+g0)*(accP[mf][nf][0]+p0);
                ot[(col+1)*68+row]   = mk0*sigf(accG[mf][nf][1]+g1)*(accP[mf][nf][1]+p1);
                ot[col*68+row+8]     = mk1*sigf(accG[mf][nf][2]+g0)*(accP[mf][nf][2]+p0);
                ot[(col+1)*68+row+8] = mk1*sigf(accG[mf][nf][3]+g1)*(accP[mf][nf][3]+p1);
            }
        __syncthreads();
        #pragma unroll
        for (int it2=0; it2<32; ++it2){
            int f = tid + it2*256;
            int r = f&63, o = f>>6;
            float v = ot[o*68 + r];
            __nv_bfloat16 hi = __float2bfloat16(v);
            __nv_bfloat16 lo = __float2bfloat16(v - __bfloat162float(hi));
            size_t base = (size_t)o*(NRES*KS2) + (size_t)i_idx*KS2 + (k0 + r);
            dst[base]       = hi;
            dst[base + 384] = lo;
        }
    } else {
        #pragma unroll
        for (int mf=0; mf<2; ++mf)
            #pragma unroll
            for (int nf=0; nf<4; ++nf){
                int col = wn*32 + nf*8 + (lane&3)*2;
                int row = wm*32 + mf*16 + (lane>>2);
                size_t R0 = (size_t)t2*64 + row;
                float g0=__ldg(GBp+col), g1=__ldg(GBp+col+1);
                *(float2*)(g_gate + R0*CH + col) =
                    make_float2(sigf(accG[mf][nf][0]+g0), sigf(accG[mf][nf][1]+g1));
                *(float2*)(g_gate + (R0+8)*CH + col) =
                    make_float2(sigf(accG[mf][nf][2]+g0), sigf(accG[mf][nf][3]+g1));
            }
    }
}

// ================= tri (R9 form): per (h,i-tile,j-tile), 2-stage BK=32 =================
// stage regions: Ah 0, Al 10240, Bh 20480, Bl 30720
#define TSTEP 40960u
#define NCH_T 12

__device__ __forceinline__ void tri_issue(int tid, int c, int buf,
    const __nv_bfloat16* Ag, const __nv_bfloat16* Bg, uint32_t sb){
    int row2 = tid>>2, seg = tid&3;
    uint32_t bofs = (uint32_t)buf*TSTEP;
    #pragma unroll
    for (int it=0; it<2; ++it){
        int row = row2 + it*64;
        uint32_t off = bofs + (uint32_t)(row*80 + seg*16);
        const __nv_bfloat16* ar = Ag + (size_t)row*KS2 + c*BK + seg*8;
        cpa(sb + off,           ar);
        cpa(sb + 10240u + off,  ar+384);
        const __nv_bfloat16* br = Bg + (size_t)row*KS2 + c*BK + seg*8;
        cpa(sb + 20480u + off,  br);
        cpa(sb + 30720u + off,  br+384);
    }
    cp_commit();
}

__global__ __launch_bounds__(256,2)
void tri_mma_kernel(){
    extern __shared__ char sm[];
    uint32_t sb = s2u(sm);

    int tid = threadIdx.x;
    int wid = tid>>5, lane = tid&31;
    int wm = wid & 1, wn = wid >> 1;
    int h = blockIdx.z, i0 = blockIdx.y*128, j0 = blockIdx.x*128;

    const __nv_bfloat16* Ag = g_as + ((size_t)h*NRES + i0)*KS2;
    const __nv_bfloat16* Bg = g_bs + ((size_t)h*NRES + j0)*KS2;

    float acc[4][4][4];
    #pragma unroll
    for (int mf=0;mf<4;++mf)
        #pragma unroll
        for (int nf=0;nf<4;++nf)
            #pragma unroll
            for (int r=0;r<4;++r) acc[mf][nf][r]=0.f;

    tri_issue(tid, 0, 0, Ag, Bg, sb);

    for (int c=0; c<NCH_T; ++c){
        int buf = c & 1;
        if (c+1 < NCH_T){ tri_issue(tid, c+1, buf^1, Ag, Bg, sb); cp_wait<1>(); }
        else cp_wait<0>();
        __syncthreads();
        uint32_t bofs = sb + (uint32_t)buf*TSTEP;
        #pragma unroll
        for (int ks=0; ks<2; ++ks){
            uint32_t ah[4][4];
            #pragma unroll
            for (int mf=0; mf<4; ++mf){
                int row = wm*64 + mf*16 + (lane&15);
                int kc  = ks*16 + (lane>>4)*8;
                ldsm4(ah[mf][0],ah[mf][1],ah[mf][2],ah[mf][3], bofs + (uint32_t)(row*LDW + kc)*2);
            }
            uint32_t bh[4][2];
            ldB(bofs + 20480u, wn, lane, ks, bh);   // Bh
            #pragma unroll
            for (int mf=0; mf<4; ++mf)
                #pragma unroll
                for (int nf=0; nf<4; ++nf)
                    mma16816(acc[mf][nf], ah[mf], bh[nf]);
            {
                uint32_t bl[4][2];
                ldB(bofs + 30720u, wn, lane, ks, bl);  // Bl
                #pragma unroll
                for (int mf=0; mf<4; ++mf)
                    #pragma unroll
                    for (int nf=0; nf<4; ++nf)
                        mma16816(acc[mf][nf], ah[mf], bl[nf]);
            }
            #pragma unroll
            for (int mf=0; mf<4; ++mf){   // reuse ah regs for Al
                int row = wm*64 + mf*16 + (lane&15);
                int kc  = ks*16 + (lane>>4)*8;
                ldsm4(ah[mf][0],ah[mf][1],ah[mf][2],ah[mf][3], bofs + 10240u + (uint32_t)(row*LDW + kc)*2);
            }
            #pragma unroll
            for (int mf=0; mf<4; ++mf)
                #pragma unroll
                for (int nf=0; nf<4; ++nf)
                    mma16816(acc[mf][nf], ah[mf], bh[nf]);
        }
        __syncthreads();
    }

    float* X = g_xt + (size_t)h*NN;
    #pragma unroll
    for (int mf=0; mf<4; ++mf){
        #pragma unroll
        for (int nf=0; nf<4; ++nf){
            int row = i0 + wm*64 + mf*16 + (lane>>2);
            int col = j0 + wn*32 + nf*8 + (lane&3)*2;
            *(float2*)(X + (size_t)row*NRES + col)     = make_float2(acc[mf][nf][0], acc[mf][nf][1]);
            *(float2*)(X + (size_t)(row+8)*NRES + col) = make_float2(acc[mf][nf][2], acc[mf][nf][3]);
        }
    }
}

// ================= outmma (FUSED LN): out = gate * (LN(x) @ z_w^T + z_b) =================
// smem: A-full [0,40960): chunk c at c*10240 (Xh), +5120 (Xl); W db at 40960 + buf*20480
// xs prologue scratch (128x66 fp32 = 33792B) overlaps W region at 40960.
#define OA_FULL 40960u
#define OWSTEP 20480u

__device__ __forceinline__ void outw_issue(int tid, int c, int buf, uint32_t sb,
                                           const __nv_bfloat16* W){
    uint32_t bofs = OA_FULL + (uint32_t)buf*OWSTEP;
    #pragma unroll
    for (int it=0; it<2; ++it){
        int idx = tid + it*256;
        int row = idx>>2, seg = idx&3;
        uint32_t off = bofs + (uint32_t)(row*80 + seg*16);
        const __nv_bfloat16* wr = W + (size_t)row*KP2 + c*BK + seg*8;
        cpa(sb + off,          wr);
        cpa(sb + 10240u + off, wr+128);
    }
    cp_commit();
}

__global__ __launch_bounds__(256,2)
void outmma_kernel(const float* __restrict__ low, const float* __restrict__ lob,
                   const float* __restrict__ zb, float* __restrict__ out)
{
    extern __shared__ char sm[];
    uint32_t sb = s2u(sm);
    float* xs = (float*)(sm + OA_FULL);   // scratch, freed before W loads
    __shared__ float mu_s[64], rs_s[64], low_s[128], lob_s[128];

    int tid=threadIdx.x, wid=tid>>5, lane=tid&31;
    int wm=wid&1, wn=wid>>1;
    int t2 = blockIdx.x;
    int row0 = t2*64;

    if (tid<128){ low_s[tid]=low[tid]; lob_s[tid]=lob[tid]; }
    #pragma unroll
    for (int it=0; it<32; ++it){
        int f = tid + it*256;
        int r = f&63, h = f>>6;
        xs[h*66 + r] = g_xt[(size_t)h*NN + row0 + r];
    }
    __syncthreads();
    #pragma unroll
    for (int rr=0;rr<8;++rr){
        int r = wid*8+rr;
        float s=0.f,q=0.f;
        #pragma unroll
        for (int m=0;m<4;++m){ float x=xs[(lane+32*m)*66 + r]; s+=x; q+=x*x; }
        #pragma unroll
        for (int o=16;o>0;o>>=1){ s+=__shfl_xor_sync(0xffffffffu,s,o); q+=__shfl_xor_sync(0xffffffffu,q,o); }
        if (lane==0){
            float mu=s*(1.f/128.f), var=q*(1.f/128.f)-mu*mu;
            mu_s[r]=mu; rs_s[r]=rsqrtf(fmaxf(var,0.f)+EPSF);
        }
    }
    __syncthreads();
    #pragma unroll
    for (int it=0; it<16; ++it){
        int f = tid + it*256;
        int r = f>>6, h2 = (f&63)*2;
        float mu=mu_s[r], rs=rs_s[r];
        float x0 = (xs[(h2+0)*66+r]-mu)*rs*low_s[h2+0]+lob_s[h2+0];
        float x1 = (xs[(h2+1)*66+r]-mu)*rs*low_s[h2+1]+lob_s[h2+1];
        __nv_bfloat16 h0=__float2bfloat16(x0), h1=__float2bfloat16(x1);
        __nv_bfloat16 l0=__float2bfloat16(x0-__bfloat162float(h0));
        __nv_bfloat16 l1=__float2bfloat16(x1-__bfloat162float(h1));
        uint32_t off = (uint32_t)(h2>>5)*10240u + (uint32_t)(r*80 + (h2&31)*2);
        *(__nv_bfloat162*)(sm + off)          = __nv_bfloat162{h0,h1};
        *(__nv_bfloat162*)(sm + off + 5120u)  = __nv_bfloat162{l0,l1};
    }
    __syncthreads();   // A-full ready; xs region now free for W streaming

    const __nv_bfloat16* W = g_ws + (size_t)5*CH*KP2;
    float acc[2][4][4];
    #pragma unroll
    for (int mf=0;mf<2;++mf)
        #pragma unroll
        for (int nf=0;nf<4;++nf)
            #pragma unroll
            for (int r=0;r<4;++r) acc[mf][nf][r]=0.f;

    outw_issue(tid, 0, 0, sb, W);

    for (int c=0; c<NCH_P; ++c){
        int buf = c & 1;
        if (c+1<NCH_P){ outw_issue(tid, c+1, buf^1, sb, W); cp_wait<1>(); }
        else cp_wait<0>();
        __syncthreads();
        uint32_t abase = sb + (uint32_t)c*10240u;
        uint32_t wbase = sb + OA_FULL + (uint32_t)buf*OWSTEP;
        #pragma unroll
        for (int ks=0; ks<2; ++ks){
            uint32_t ah[2][4], al[2][4];
            #pragma unroll
            for (int mf=0; mf<2; ++mf){
                int row = wm*32 + mf*16 + (lane&15);
                int kc  = ks*16 + (lane>>4)*8;
                uint32_t ro = (uint32_t)(row*LDW + kc)*2;
                ldsm4(ah[mf][0],ah[mf][1],ah[mf][2],ah[mf][3], abase + ro);
                ldsm4(al[mf][0],al[mf][1],al[mf][2],al[mf][3], abase + 5120u + ro);
            }
            uint32_t bf[4][2];
            ldB(wbase, wn, lane, ks, bf);            // Wh
            #pragma unroll
            for (int mf=0; mf<2; ++mf)
                #pragma unroll
                for (int nf=0; nf<4; ++nf){
                    mma16816(acc[mf][nf], ah[mf], bf[nf]);
                    mma16816(acc[mf][nf], al[mf], bf[nf]);
                }
            ldB(wbase + 10240u, wn, lane, ks, bf);   // Wl
            #pragma unroll
            for (int mf=0; mf<2; ++mf)
                #pragma unroll
                for (int nf=0; nf<4; ++nf)
                    mma16816(acc[mf][nf], ah[mf], bf[nf]);
        }
        __syncthreads();
    }

    #pragma unroll
    for (int mf=0; mf<2; ++mf)
        #pragma unroll
        for (int nf=0; nf<4; ++nf){
            int col = wn*32 + nf*8 + (lane&3)*2;
            int row = wm*32 + mf*16 + (lane>>2);
            size_t R0 = (size_t)row0 + row;
            float2 zb2 = *(const float2*)(zb + col);
            float2 ga = *(const float2*)(g_gate + R0*CH + col);
            float2 gb2 = *(const float2*)(g_gate + (R0+8)*CH + col);
            *(float2*)(out + R0*CH + col) =
                make_float2(ga.x*(acc[mf][nf][0]+zb2.x), ga.y*(acc[mf][nf][1]+zb2.y));
            *(float2*)(out + (R0+8)*CH + col) =
                make_float2(gb2.x*(acc[mf][nf][2]+zb2.x), gb2.y*(acc[mf][nf][3]+zb2.y));
        }
}

extern "C" void kernel_launch(void* const* d_in, const int* in_sizes, int n_in,
                              void* d_out, int out_size) {
    const float* z      = (const float*)d_in[0];
    const float* mask   = (const float*)d_in[1];
    const float* ln_in_w= (const float*)d_in[2];
    const float* ln_in_b= (const float*)d_in[3];
    const float* a_g_w  = (const float*)d_in[4];
    const float* a_g_b  = (const float*)d_in[5];
    const float* a_p_w  = (const float*)d_in[6];
    const float* a_p_b  = (const float*)d_in[7];
    const float* b_g_w  = (const float*)d_in[8];
    const float* b_g_b  = (const float*)d_in[9];
    const float* b_p_w  = (const float*)d_in[10];
    const float* b_p_b  = (const float*)d_in[11];
    const float* g_w    = (const float*)d_in[12];
    const float* g_b    = (const float*)d_in[13];
    const float* ln_out_w=(const float*)d_in[14];
    const float* ln_out_b=(const float*)d_in[15];
    const float* z_w    = (const float*)d_in[16];
    const float* z_b    = (const float*)d_in[17];
    float* out = (float*)d_out;

    cudaFuncSetAttribute(projmma_kernel, cudaFuncAttributeMaxDynamicSharedMemorySize, 2*PSTEP);
    cudaFuncSetAttribute(tri_mma_kernel, cudaFuncAttributeMaxDynamicSharedMemorySize, 2*TSTEP);
    cudaFuncSetAttribute(outmma_kernel, cudaFuncAttributeMaxDynamicSharedMemorySize, 81920);

    wsplit_kernel<<<6,256>>>(a_g_w, a_p_w, b_g_w, b_p_w, g_w, z_w);
    ln_split_kernel<<<NN/8,256>>>(z, ln_in_w, ln_in_b);
    projmma_kernel<<<dim3(3,2304),256,2*PSTEP>>>(mask, a_g_b, a_p_b, b_g_b, b_p_b, g_b);
    tri_mma_kernel<<<dim3(3,3,CH),256,2*TSTEP>>>();
    outmma_kernel<<<NN/64,256,81920>>>(ln_out_w, ln_out_b, z_b, out);
}

// round 13
// speedup vs baseline: 1.2674x; 1.1073x over previous
#include <cuda_runtime.h>
#include <cuda_bf16.h>
#include <cstdint>

#define NRES 384
#define CH 128
#define NN (NRES*NRES)
#define EPSF 1e-5f
#define KS2 768           // triangle operand row: [hi(384)|lo(384)]
#define KP2 256           // proj/out row: [hi(128)|lo(128)]
#define BK 32
#define LDW 40            // bf16 per padded smem row (80B)

// ---- scratch (device globals; no allocation) ----
__device__ __nv_bfloat16 g_as[(size_t)CH*NRES*KS2];
__device__ __nv_bfloat16 g_bs[(size_t)CH*NRES*KS2];
__device__ __nv_bfloat16 g_ws[(size_t)6*CH*KP2];
__device__ float g_gate[(size_t)NN*CH];
__device__ float g_xt[(size_t)CH*NN];

__device__ __forceinline__ float sigf(float x){ return 1.f/(1.f+__expf(-x)); }

__device__ __forceinline__ uint32_t s2u(const void* p){
    uint32_t a;
    asm("{ .reg .u64 t; cvta.to.shared.u64 t, %1; cvt.u32.u64 %0, t; }" : "=r"(a) : "l"(p));
    return a;
}
__device__ __forceinline__ void ldsm4(uint32_t &r0,uint32_t &r1,uint32_t &r2,uint32_t &r3,uint32_t a){
    asm volatile("ldmatrix.sync.aligned.m8n8.x4.shared.b16 {%0,%1,%2,%3}, [%4];"
        : "=r"(r0),"=r"(r1),"=r"(r2),"=r"(r3) : "r"(a));
}
__device__ __forceinline__ void mma16816(float* d, const uint32_t* a, const uint32_t* b){
    asm volatile("mma.sync.aligned.m16n8k16.row.col.f32.bf16.bf16.f32 "
        "{%0,%1,%2,%3}, {%4,%5,%6,%7}, {%8,%9}, {%0,%1,%2,%3};"
        : "+f"(d[0]),"+f"(d[1]),"+f"(d[2]),"+f"(d[3])
        : "r"(a[0]),"r"(a[1]),"r"(a[2]),"r"(a[3]), "r"(b[0]),"r"(b[1]));
}
__device__ __forceinline__ void cpa(uint32_t d, const void* s){
    asm volatile("cp.async.ca.shared.global [%0], [%1], 16;" :: "r"(d), "l"(s) : "memory");
}
__device__ __forceinline__ void cp_commit(){ asm volatile("cp.async.commit_group;" ::: "memory"); }
template<int N> __device__ __forceinline__ void cp_wait(){ asm volatile("cp.async.wait_group %0;" :: "n"(N) : "memory"); }

// B fragments: 4 n8k16 tiles (32 n-rows) from padded smem (LDW bf16/row)
__device__ __forceinline__ void ldB(uint32_t base, int wn, int lane, int ks, uint32_t bf[4][2]){
    int kc = ks*16 + ((lane>>3)&1)*8;
    #pragma unroll
    for (int nf2=0; nf2<2; ++nf2){
        int nrow = wn*32 + nf2*16 + (lane&7) + ((lane>>4)<<3);
        uint32_t r0,r1,r2,r3;
        ldsm4(r0,r1,r2,r3, base + (uint32_t)(nrow*LDW + kc)*2);
        bf[nf2*2+0][0]=r0; bf[nf2*2+0][1]=r1;
        bf[nf2*2+1][0]=r2; bf[nf2*2+1][1]=r3;
    }
}

// ---- split 6 weights into bf16 [Wh|Wl] ----
__global__ void wsplit_kernel(const float* w0, const float* w1, const float* w2,
                              const float* w3, const float* w4, const float* w5){
    const float* srcs[6] = {w0,w1,w2,w3,w4,w5};
    const float* W = srcs[blockIdx.x];
    __nv_bfloat16* dst = g_ws + (size_t)blockIdx.x*CH*KP2;
    for (int it=0; it<64; ++it){
        int idx = threadIdx.x + it*256;
        int o = idx>>7, k = idx&127;
        float v = W[idx];
        __nv_bfloat16 hi = __float2bfloat16(v);
        __nv_bfloat16 lo = __float2bfloat16(v - __bfloat162float(hi));
        dst[(size_t)o*KP2 + k]       = hi;
        dst[(size_t)o*KP2 + 128 + k] = lo;
    }
}

// ================= projmma (FUSED LN): grid (3, 2304), A resident, weight streaming =================
// smem: A-full [0,40960): chunk c at c*10240 (hi), +5120 (lo); W db at 40960 + buf*20480 (h +0, l +10240)
#define PA_FULL 40960u
#define PWSTEP 20480u
#define NCH_P 4

__device__ __forceinline__ void wissue(int tid, int c, int buf, uint32_t sb,
                                       const __nv_bfloat16* W){
    #pragma unroll
    for (int it=0; it<2; ++it){
        int idx = tid + it*256;
        int row = idx>>2, seg = idx&3;
        uint32_t off = PA_FULL + (uint32_t)buf*PWSTEP + (uint32_t)(row*80 + seg*16);
        const __nv_bfloat16* wr = W + (size_t)row*KP2 + c*BK + seg*8;
        cpa(sb + off,          wr);
        cpa(sb + off + 10240u, wr + 128);
    }
    cp_commit();
}

__global__ __launch_bounds__(256,2)
void projmma_kernel(const float* __restrict__ z, const float* __restrict__ mask_,
                    const float* __restrict__ lnw, const float* __restrict__ lnb,
                    const float* __restrict__ agb, const float* __restrict__ apb,
                    const float* __restrict__ bgb, const float* __restrict__ bpb,
                    const float* __restrict__ gb_)
{
    extern __shared__ char sm[];
    uint32_t sb = s2u(sm);
    float* ot = (float*)sm;

    int tid=threadIdx.x, wid=tid>>5, lane=tid&31;
    int wm=wid&1, wn=wid>>1;
    int ph = blockIdx.x, t2 = blockIdx.y;   // phase fastest: phases of one tile share L2
    bool hasP = ph<2;
    const __nv_bfloat16* WG = g_ws + (size_t)(hasP ? 2*ph : 4)*CH*KP2;
    const __nv_bfloat16* WP = g_ws + (size_t)(hasP ? 2*ph+1 : 4)*CH*KP2;
    const float* GBp = (ph==0)?agb:((ph==1)?bgb:gb_);
    const float* PBp = (ph==0)?apb:bpb;
    const float* zrow = z + (size_t)t2*64*CH;

    // ---- prologue: LN(z) 64 rows -> split bf16 into resident A-full ----
    {
        float4 w4 = *(const float4*)(lnw + lane*4);
        float4 b4 = *(const float4*)(lnb + lane*4);
        uint32_t abase = sb + (uint32_t)(lane>>3)*10240u + (uint32_t)((lane&7)*8);
        #pragma unroll
        for (int rr=0; rr<8; ++rr){
            int r = wid*8 + rr;
            float4 v = *(const float4*)(zrow + (size_t)r*CH + lane*4);
            float s = v.x+v.y+v.z+v.w;
            float q = v.x*v.x+v.y*v.y+v.z*v.z+v.w*v.w;
            #pragma unroll
            for (int o=16;o>0;o>>=1){ s+=__shfl_xor_sync(0xffffffffu,s,o); q+=__shfl_xor_sync(0xffffffffu,q,o); }
            float mu=s*(1.f/128.f), var=q*(1.f/128.f)-mu*mu;
            float rs=rsqrtf(fmaxf(var,0.f)+EPSF);
            float n0=(v.x-mu)*rs*w4.x+b4.x, n1=(v.y-mu)*rs*w4.y+b4.y;
            float n2=(v.z-mu)*rs*w4.z+b4.z, n3=(v.w-mu)*rs*w4.w+b4.w;
            __nv_bfloat16 h0=__float2bfloat16(n0), h1=__float2bfloat16(n1);
            __nv_bfloat16 h2=__float2bfloat16(n2), h3=__float2bfloat16(n3);
            __nv_bfloat16 l0=__float2bfloat16(n0-__bfloat162float(h0));
            __nv_bfloat16 l1=__float2bfloat16(n1-__bfloat162float(h1));
            __nv_bfloat16 l2=__float2bfloat16(n2-__bfloat162float(h2));
            __nv_bfloat16 l3=__float2bfloat16(n3-__bfloat162float(h3));
            uint32_t off = abase + (uint32_t)(r*80);
            *(__nv_bfloat162*)(sm + (off - sb))          = __nv_bfloat162{h0,h1};
            *(__nv_bfloat162*)(sm + (off - sb) + 4)      = __nv_bfloat162{h2,h3};
            *(__nv_bfloat162*)(sm + (off - sb) + 5120)   = __nv_bfloat162{l0,l1};
            *(__nv_bfloat162*)(sm + (off - sb) + 5124)   = __nv_bfloat162{l2,l3};
        }
    }

    float accG[2][4][4], accP[2][4][4];
    #pragma unroll
    for (int mf=0;mf<2;++mf)
        #pragma unroll
        for (int nf=0;nf<4;++nf)
            #pragma unroll
            for (int r=0;r<4;++r){ accG[mf][nf][r]=0.f; accP[mf][nf][r]=0.f; }

    // ---- pass G ----
    wissue(tid, 0, 0, sb, WG);
    for (int c=0; c<NCH_P; ++c){
        int buf = c & 1;
        if (c+1<NCH_P){ wissue(tid, c+1, buf^1, sb, WG); cp_wait<1>(); }
        else cp_wait<0>();
        __syncthreads();
        uint32_t abase = sb + (uint32_t)c*10240u;
        uint32_t wbase = sb + PA_FULL + (uint32_t)buf*PWSTEP;
        #pragma unroll
        for (int ks=0; ks<2; ++ks){
            uint32_t ah[2][4], al[2][4];
            #pragma unroll
            for (int mf=0; mf<2; ++mf){
                int row = wm*32 + mf*16 + (lane&15);
                int kc  = ks*16 + (lane>>4)*8;
                uint32_t ro = (uint32_t)(row*LDW + kc)*2;
                ldsm4(ah[mf][0],ah[mf][1],ah[mf][2],ah[mf][3], abase + ro);
                ldsm4(al[mf][0],al[mf][1],al[mf][2],al[mf][3], abase + 5120u + ro);
            }
            uint32_t bf[4][2];
            ldB(wbase, wn, lane, ks, bf);            // Gh
            #pragma unroll
            for (int mf=0; mf<2; ++mf)
                #pragma unroll
                for (int nf=0; nf<4; ++nf){
                    mma16816(accG[mf][nf], ah[mf], bf[nf]);
                    mma16816(accG[mf][nf], al[mf], bf[nf]);
                }
            ldB(wbase + 10240u, wn, lane, ks, bf);   // Gl
            #pragma unroll
            for (int mf=0; mf<2; ++mf)
                #pragma unroll
                for (int nf=0; nf<4; ++nf)
                    mma16816(accG[mf][nf], ah[mf], bf[nf]);
        }
        __syncthreads();
    }

    // ---- pass P (hasP phases only) ----
    if (hasP){
        wissue(tid, 0, 0, sb, WP);
        for (int c=0; c<NCH_P; ++c){
            int buf = c & 1;
            if (c+1<NCH_P){ wissue(tid, c+1, buf^1, sb, WP); cp_wait<1>(); }
            else cp_wait<0>();
            __syncthreads();
            uint32_t abase = sb + (uint32_t)c*10240u;
            uint32_t wbase = sb + PA_FULL + (uint32_t)buf*PWSTEP;
            #pragma unroll
            for (int ks=0; ks<2; ++ks){
                uint32_t ah[2][4], al[2][4];
                #pragma unroll
                for (int mf=0; mf<2; ++mf){
                    int row = wm*32 + mf*16 + (lane&15);
                    int kc  = ks*16 + (lane>>4)*8;
                    uint32_t ro = (uint32_t)(row*LDW + kc)*2;
                    ldsm4(ah[mf][0],ah[mf][1],ah[mf][2],ah[mf][3], abase + ro);
                    ldsm4(al[mf][0],al[mf][1],al[mf][2],al[mf][3], abase + 5120u + ro);
                }
                uint32_t bf[4][2];
                ldB(wbase, wn, lane, ks, bf);            // Ph
                #pragma unroll
                for (int mf=0; mf<2; ++mf)
                    #pragma unroll
                    for (int nf=0; nf<4; ++nf){
                        mma16816(accP[mf][nf], ah[mf], bf[nf]);
                        mma16816(accP[mf][nf], al[mf], bf[nf]);
                    }
                ldB(wbase + 10240u, wn, lane, ks, bf);   // Pl
                #pragma unroll
                for (int mf=0; mf<2; ++mf)
                    #pragma unroll
                    for (int nf=0; nf<4; ++nf)
                        mma16816(accP[mf][nf], ah[mf], bf[nf]);
            }
            __syncthreads();
        }
    }

    // ---- epilogue ----
    if (hasP){
        __nv_bfloat16* dst = ph ? g_bs : g_as;
        int i_idx = t2/6, k0 = (t2%6)*64;
        #pragma unroll
        for (int mf=0; mf<2; ++mf)
            #pragma unroll
            for (int nf=0; nf<4; ++nf){
                int col = wn*32 + nf*8 + (lane&3)*2;
                int row = wm*32 + mf*16 + (lane>>2);
                float mk0 = __ldg(mask_ + t2*64 + row);
                float mk1 = __ldg(mask_ + t2*64 + row + 8);
                float g0=__ldg(GBp+col), g1=__ldg(GBp+col+1);
                float p0=__ldg(PBp+col), p1=__ldg(PBp+col+1);
                ot[col*68+row]       = mk0*sigf(accG[mf][nf][0]+g0)*(accP[mf][nf][0]+p0);
                ot[(col+1)*68+row]   = mk0*sigf(accG[mf][nf][1]+g1)*(accP[mf][nf][1]+p1);
                ot[col*68+row+8]     = mk1*sigf(accG[mf][nf][2]+g0)*(accP[mf][nf][2]+p0);
                ot[(col+1)*68+row+8] = mk1*sigf(accG[mf][nf][3]+g1)*(accP[mf][nf][3]+p1);
            }
        __syncthreads();
        #pragma unroll
        for (int it2=0; it2<32; ++it2){
            int f = tid + it2*256;
            int r = f&63, o = f>>6;
            float v = ot[o*68 + r];
            __nv_bfloat16 hi = __float2bfloat16(v);
            __nv_bfloat16 lo = __float2bfloat16(v - __bfloat162float(hi));
            size_t base = (size_t)o*(NRES*KS2) + (size_t)i_idx*KS2 + (k0 + r);
            dst[base]       = hi;
            dst[base + 384] = lo;
        }
    } else {
        #pragma unroll
        for (int mf=0; mf<2; ++mf)
            #pragma unroll
            for (int nf=0; nf<4; ++nf){
                int col = wn*32 + nf*8 + (lane&3)*2;
                int row = wm*32 + mf*16 + (lane>>2);
                size_t R0 = (size_t)t2*64 + row;
                float g0=__ldg(GBp+col), g1=__ldg(GBp+col+1);
                *(float2*)(g_gate + R0*CH + col) =
                    make_float2(sigf(accG[mf][nf][0]+g0), sigf(accG[mf][nf][1]+g1));
                *(float2*)(g_gate + (R0+8)*CH + col) =
                    make_float2(sigf(accG[mf][nf][2]+g0), sigf(accG[mf][nf][3]+g1));
            }
    }
}

// ================= tri (R9 form): per (h,i-tile,j-tile), 2-stage BK=32 =================
// stage regions: Ah 0, Al 10240, Bh 20480, Bl 30720
#define TSTEP 40960u
#define NCH_T 12

__device__ __forceinline__ void tri_issue(int tid, int c, int buf,
    const __nv_bfloat16* Ag, const __nv_bfloat16* Bg, uint32_t sb){
    int row2 = tid>>2, seg = tid&3;
    uint32_t bofs = (uint32_t)buf*TSTEP;
    #pragma unroll
    for (int it=0; it<2; ++it){
        int row = row2 + it*64;
        uint32_t off = bofs + (uint32_t)(row*80 + seg*16);
        const __nv_bfloat16* ar = Ag + (size_t)row*KS2 + c*BK + seg*8;
        cpa(sb + off,           ar);
        cpa(sb + 10240u + off,  ar+384);
        const __nv_bfloat16* br = Bg + (size_t)row*KS2 + c*BK + seg*8;
        cpa(sb + 20480u + off,  br);
        cpa(sb + 30720u + off,  br+384);
    }
    cp_commit();
}

__global__ __launch_bounds__(256,2)
void tri_mma_kernel(){
    extern __shared__ char sm[];
    uint32_t sb = s2u(sm);

    int tid = threadIdx.x;
    int wid = tid>>5, lane = tid&31;
    int wm = wid & 1, wn = wid >> 1;
    int h = blockIdx.z, i0 = blockIdx.y*128, j0 = blockIdx.x*128;

    const __nv_bfloat16* Ag = g_as + ((size_t)h*NRES + i0)*KS2;
    const __nv_bfloat16* Bg = g_bs + ((size_t)h*NRES + j0)*KS2;

    float acc[4][4][4];
    #pragma unroll
    for (int mf=0;mf<4;++mf)
        #pragma unroll
        for (int nf=0;nf<4;++nf)
            #pragma unroll
            for (int r=0;r<4;++r) acc[mf][nf][r]=0.f;

    tri_issue(tid, 0, 0, Ag, Bg, sb);

    for (int c=0; c<NCH_T; ++c){
        int buf = c & 1;
        if (c+1 < NCH_T){ tri_issue(tid, c+1, buf^1, Ag, Bg, sb); cp_wait<1>(); }
        else cp_wait<0>();
        __syncthreads();
        uint32_t bofs = sb + (uint32_t)buf*TSTEP;
        #pragma unroll
        for (int ks=0; ks<2; ++ks){
            uint32_t ah[4][4];
            #pragma unroll
            for (int mf=0; mf<4; ++mf){
                int row = wm*64 + mf*16 + (lane&15);
                int kc  = ks*16 + (lane>>4)*8;
                ldsm4(ah[mf][0],ah[mf][1],ah[mf][2],ah[mf][3], bofs + (uint32_t)(row*LDW + kc)*2);
            }
            uint32_t bh[4][2];
            ldB(bofs + 20480u, wn, lane, ks, bh);   // Bh
            #pragma unroll
            for (int mf=0; mf<4; ++mf)
                #pragma unroll
                for (int nf=0; nf<4; ++nf)
                    mma16816(acc[mf][nf], ah[mf], bh[nf]);
            {
                uint32_t bl[4][2];
                ldB(bofs + 30720u, wn, lane, ks, bl);  // Bl
                #pragma unroll
                for (int mf=0; mf<4; ++mf)
                    #pragma unroll
                    for (int nf=0; nf<4; ++nf)
                        mma16816(acc[mf][nf], ah[mf], bl[nf]);
            }
            #pragma unroll
            for (int mf=0; mf<4; ++mf){   // reuse ah regs for Al
                int row = wm*64 + mf*16 + (lane&15);
                int kc  = ks*16 + (lane>>4)*8;
                ldsm4(ah[mf][0],ah[mf][1],ah[mf][2],ah[mf][3], bofs + 10240u + (uint32_t)(row*LDW + kc)*2);
            }
            #pragma unroll
            for (int mf=0; mf<4; ++mf)
                #pragma unroll
                for (int nf=0; nf<4; ++nf)
                    mma16816(acc[mf][nf], ah[mf], bh[nf]);
        }
        __syncthreads();
    }

    float* X = g_xt + (size_t)h*NN;
    #pragma unroll
    for (int mf=0; mf<4; ++mf){
        #pragma unroll
        for (int nf=0; nf<4; ++nf){
            int row = i0 + wm*64 + mf*16 + (lane>>2);
            int col = j0 + wn*32 + nf*8 + (lane&3)*2;
            *(float2*)(X + (size_t)row*NRES + col)     = make_float2(acc[mf][nf][0], acc[mf][nf][1]);
            *(float2*)(X + (size_t)(row+8)*NRES + col) = make_float2(acc[mf][nf][2], acc[mf][nf][3]);
        }
    }
}

// ================= outmma (FUSED LN): out = gate * (LN(x) @ z_w^T + z_b) =================
// smem: A-full [0,40960): chunk c at c*10240 (Xh), +5120 (Xl); W db at 40960 + buf*20480
// xs prologue scratch (128x66 fp32 = 33792B) overlaps W region at 40960.
#define OA_FULL 40960u
#define OWSTEP 20480u

__device__ __forceinline__ void outw_issue(int tid, int c, int buf, uint32_t sb,
                                           const __nv_bfloat16* W){
    uint32_t bofs = OA_FULL + (uint32_t)buf*OWSTEP;
    #pragma unroll
    for (int it=0; it<2; ++it){
        int idx = tid + it*256;
        int row = idx>>2, seg = idx&3;
        uint32_t off = bofs + (uint32_t)(row*80 + seg*16);
        const __nv_bfloat16* wr = W + (size_t)row*KP2 + c*BK + seg*8;
        cpa(sb + off,          wr);
        cpa(sb + 10240u + off, wr+128);
    }
    cp_commit();
}

__global__ __launch_bounds__(256,2)
void outmma_kernel(const float* __restrict__ low, const float* __restrict__ lob,
                   const float* __restrict__ zb, float* __restrict__ out)
{
    extern __shared__ char sm[];
    uint32_t sb = s2u(sm);
    float* xs = (float*)(sm + OA_FULL);   // scratch, freed before W loads
    __shared__ float mu_s[64], rs_s[64], low_s[128], lob_s[128];

    int tid=threadIdx.x, wid=tid>>5, lane=tid&31;
    int wm=wid&1, wn=wid>>1;
    int t2 = blockIdx.x;
    int row0 = t2*64;

    if (tid<128){ low_s[tid]=low[tid]; lob_s[tid]=lob[tid]; }
    #pragma unroll
    for (int it=0; it<32; ++it){
        int f = tid + it*256;
        int r = f&63, h = f>>6;
        xs[h*66 + r] = g_xt[(size_t)h*NN + row0 + r];
    }
    __syncthreads();
    #pragma unroll
    for (int rr=0;rr<8;++rr){
        int r = wid*8+rr;
        float s=0.f,q=0.f;
        #pragma unroll
        for (int m=0;m<4;++m){ float x=xs[(lane+32*m)*66 + r]; s+=x; q+=x*x; }
        #pragma unroll
        for (int o=16;o>0;o>>=1){ s+=__shfl_xor_sync(0xffffffffu,s,o); q+=__shfl_xor_sync(0xffffffffu,q,o); }
        if (lane==0){
            float mu=s*(1.f/128.f), var=q*(1.f/128.f)-mu*mu;
            mu_s[r]=mu; rs_s[r]=rsqrtf(fmaxf(var,0.f)+EPSF);
        }
    }
    __syncthreads();
    #pragma unroll
    for (int it=0; it<16; ++it){
        int f = tid + it*256;
        int r = f>>6, h2 = (f&63)*2;
        float mu=mu_s[r], rs=rs_s[r];
        float x0 = (xs[(h2+0)*66+r]-mu)*rs*low_s[h2+0]+lob_s[h2+0];
        float x1 = (xs[(h2+1)*66+r]-mu)*rs*low_s[h2+1]+lob_s[h2+1];
        __nv_bfloat16 h0=__float2bfloat16(x0), h1=__float2bfloat16(x1);
        __nv_bfloat16 l0=__float2bfloat16(x0-__bfloat162float(h0));
        __nv_bfloat16 l1=__float2bfloat16(x1-__bfloat162float(h1));
        uint32_t off = (uint32_t)(h2>>5)*10240u + (uint32_t)(r*80 + (h2&31)*2);
        *(__nv_bfloat162*)(sm + off)          = __nv_bfloat162{h0,h1};
        *(__nv_bfloat162*)(sm + off + 5120u)  = __nv_bfloat162{l0,l1};
    }
    __syncthreads();   // A-full ready; xs region now free for W streaming

    const __nv_bfloat16* W = g_ws + (size_t)5*CH*KP2;
    float acc[2][4][4];
    #pragma unroll
    for (int mf=0;mf<2;++mf)
        #pragma unroll
        for (int nf=0;nf<4;++nf)
            #pragma unroll
            for (int r=0;r<4;++r) acc[mf][nf][r]=0.f;

    outw_issue(tid, 0, 0, sb, W);

    for (int c=0; c<NCH_P; ++c){
        int buf = c & 1;
        if (c+1<NCH_P){ outw_issue(tid, c+1, buf^1, sb, W); cp_wait<1>(); }
        else cp_wait<0>();
        __syncthreads();
        uint32_t abase = sb + (uint32_t)c*10240u;
        uint32_t wbase = sb + OA_FULL + (uint32_t)buf*OWSTEP;
        #pragma unroll
        for (int ks=0; ks<2; ++ks){
            uint32_t ah[2][4], al[2][4];
            #pragma unroll
            for (int mf=0; mf<2; ++mf){
                int row = wm*32 + mf*16 + (lane&15);
                int kc  = ks*16 + (lane>>4)*8;
                uint32_t ro = (uint32_t)(row*LDW + kc)*2;
                ldsm4(ah[mf][0],ah[mf][1],ah[mf][2],ah[mf][3], abase + ro);
                ldsm4(al[mf][0],al[mf][1],al[mf][2],al[mf][3], abase + 5120u + ro);
            }
            uint32_t bf[4][2];
            ldB(wbase, wn, lane, ks, bf);            // Wh
            #pragma unroll
            for (int mf=0; mf<2; ++mf)
                #pragma unroll
                for (int nf=0; nf<4; ++nf){
                    mma16816(acc[mf][nf], ah[mf], bf[nf]);
                    mma16816(acc[mf][nf], al[mf], bf[nf]);
                }
            ldB(wbase + 10240u, wn, lane, ks, bf);   // Wl
            #pragma unroll
            for (int mf=0; mf<2; ++mf)
                #pragma unroll
                for (int nf=0; nf<4; ++nf)
                    mma16816(acc[mf][nf], ah[mf], bf[nf]);
        }
        __syncthreads();
    }

    #pragma unroll
    for (int mf=0; mf<2; ++mf)
        #pragma unroll
        for (int nf=0; nf<4; ++nf){
            int col = wn*32 + nf*8 + (lane&3)*2;
            int row = wm*32 + mf*16 + (lane>>2);
            size_t R0 = (size_t)row0 + row;
            float2 zb2 = *(const float2*)(zb + col);
            float2 ga = *(const float2*)(g_gate + R0*CH + col);
            float2 gb2 = *(const float2*)(g_gate + (R0+8)*CH + col);
            *(float2*)(out + R0*CH + col) =
                make_float2(ga.x*(acc[mf][nf][0]+zb2.x), ga.y*(acc[mf][nf][1]+zb2.y));
            *(float2*)(out + (R0+8)*CH + col) =
                make_float2(gb2.x*(acc[mf][nf][2]+zb2.x), gb2.y*(acc[mf][nf][3]+zb2.y));
        }
}

extern "C" void kernel_launch(void* const* d_in, const int* in_sizes, int n_in,
                              void* d_out, int out_size) {
    const float* z      = (const float*)d_in[0];
    const float* mask   = (const float*)d_in[1];
    const float* ln_in_w= (const float*)d_in[2];
    const float* ln_in_b= (const float*)d_in[3];
    const float* a_g_w  = (const float*)d_in[4];
    const float* a_g_b  = (const float*)d_in[5];
    const float* a_p_w  = (const float*)d_in[6];
    const float* a_p_b  = (const float*)d_in[7];
    const float* b_g_w  = (const float*)d_in[8];
    const float* b_g_b  = (const float*)d_in[9];
    const float* b_p_w  = (const float*)d_in[10];
    const float* b_p_b  = (const float*)d_in[11];
    const float* g_w    = (const float*)d_in[12];
    const float* g_b    = (const float*)d_in[13];
    const float* ln_out_w=(const float*)d_in[14];
    const float* ln_out_b=(const float*)d_in[15];
    const float* z_w    = (const float*)d_in[16];
    const float* z_b    = (const float*)d_in[17];
    float* out = (float*)d_out;

    cudaFuncSetAttribute(projmma_kernel, cudaFuncAttributeMaxDynamicSharedMemorySize, 81920);
    cudaFuncSetAttribute(tri_mma_kernel, cudaFuncAttributeMaxDynamicSharedMemorySize, 2*TSTEP);
    cudaFuncSetAttribute(outmma_kernel, cudaFuncAttributeMaxDynamicSharedMemorySize, 81920);

    wsplit_kernel<<<6,256>>>(a_g_w, a_p_w, b_g_w, b_p_w, g_w, z_w);
    projmma_kernel<<<dim3(3,2304),256,81920>>>(z, mask, ln_in_w, ln_in_b,
                                               a_g_b, a_p_b, b_g_b, b_p_b, g_b);
    tri_mma_kernel<<<dim3(3,3,CH),256,2*TSTEP>>>();
    outmma_kernel<<<NN/64,256,81920>>>(ln_out_w, ln_out_b, z_b, out);
}

// round 14
// speedup vs baseline: 1.2698x; 1.0019x over previous
#include <cuda_runtime.h>
#include <cuda_bf16.h>
#include <cstdint>

#define NRES 384
#define CH 128
#define NN (NRES*NRES)
#define EPSF 1e-5f
#define KS2 768           // triangle operand row: [hi(384)|lo(384)]
#define KP2 256           // proj/out row: [hi(128)|lo(128)]
#define BK 32
#define LDW 40            // bf16 per padded smem row (80B)

// ---- scratch (device globals; no allocation) ----
__device__ __nv_bfloat16 g_as[(size_t)CH*NRES*KS2];
__device__ __nv_bfloat16 g_bs[(size_t)CH*NRES*KS2];
__device__ __nv_bfloat16 g_ws[(size_t)6*CH*KP2];
__device__ float g_gate[(size_t)NN*CH];
__device__ float g_xt[(size_t)CH*NN];

__device__ __forceinline__ float sigf(float x){ return 1.f/(1.f+__expf(-x)); }

__device__ __forceinline__ uint32_t s2u(const void* p){
    uint32_t a;
    asm("{ .reg .u64 t; cvta.to.shared.u64 t, %1; cvt.u32.u64 %0, t; }" : "=r"(a) : "l"(p));
    return a;
}
__device__ __forceinline__ void ldsm4(uint32_t &r0,uint32_t &r1,uint32_t &r2,uint32_t &r3,uint32_t a){
    asm volatile("ldmatrix.sync.aligned.m8n8.x4.shared.b16 {%0,%1,%2,%3}, [%4];"
        : "=r"(r0),"=r"(r1),"=r"(r2),"=r"(r3) : "r"(a));
}
__device__ __forceinline__ void mma16816(float* d, const uint32_t* a, const uint32_t* b){
    asm volatile("mma.sync.aligned.m16n8k16.row.col.f32.bf16.bf16.f32 "
        "{%0,%1,%2,%3}, {%4,%5,%6,%7}, {%8,%9}, {%0,%1,%2,%3};"
        : "+f"(d[0]),"+f"(d[1]),"+f"(d[2]),"+f"(d[3])
        : "r"(a[0]),"r"(a[1]),"r"(a[2]),"r"(a[3]), "r"(b[0]),"r"(b[1]));
}
__device__ __forceinline__ void cpa(uint32_t d, const void* s){
    asm volatile("cp.async.ca.shared.global [%0], [%1], 16;" :: "r"(d), "l"(s) : "memory");
}
__device__ __forceinline__ void cp_commit(){ asm volatile("cp.async.commit_group;" ::: "memory"); }
template<int N> __device__ __forceinline__ void cp_wait(){ asm volatile("cp.async.wait_group %0;" :: "n"(N) : "memory"); }

// B fragments: 4 n8k16 tiles (32 n-rows) from padded smem (LDW bf16/row)
__device__ __forceinline__ void ldB(uint32_t base, int wn, int lane, int ks, uint32_t bf[4][2]){
    int kc = ks*16 + ((lane>>3)&1)*8;
    #pragma unroll
    for (int nf2=0; nf2<2; ++nf2){
        int nrow = wn*32 + nf2*16 + (lane&7) + ((lane>>4)<<3);
        uint32_t r0,r1,r2,r3;
        ldsm4(r0,r1,r2,r3, base + (uint32_t)(nrow*LDW + kc)*2);
        bf[nf2*2+0][0]=r0; bf[nf2*2+0][1]=r1;
        bf[nf2*2+1][0]=r2; bf[nf2*2+1][1]=r3;
    }
}

// ---- split 6 weights into bf16 [Wh|Wl] ----
__global__ void wsplit_kernel(const float* w0, const float* w1, const float* w2,
                              const float* w3, const float* w4, const float* w5){
    const float* srcs[6] = {w0,w1,w2,w3,w4,w5};
    const float* W = srcs[blockIdx.x];
    __nv_bfloat16* dst = g_ws + (size_t)blockIdx.x*CH*KP2;
    for (int it=0; it<64; ++it){
        int idx = threadIdx.x + it*256;
        int o = idx>>7, k = idx&127;
        float v = W[idx];
        __nv_bfloat16 hi = __float2bfloat16(v);
        __nv_bfloat16 lo = __float2bfloat16(v - __bfloat162float(hi));
        dst[(size_t)o*KP2 + k]       = hi;
        dst[(size_t)o*KP2 + 128 + k] = lo;
    }
}

// ================= projmma (FUSED LN + ALL 3 PHASES): grid (2304) =================
// smem: A-full [0,40960): chunk c at c*10240 (hi), +5120 (lo)
//       W db at 40960 + buf*20480 (h +0, l +10240)
//       epilogue ot (float[128*68] = 34816B) overlays the W region at 40960
#define PA_FULL 40960u
#define PWSTEP 20480u
#define NCH_P 4

__device__ __forceinline__ void wissue(int tid, int c, int buf, uint32_t sb,
                                       const __nv_bfloat16* W){
    #pragma unroll
    for (int it=0; it<2; ++it){
        int idx = tid + it*256;
        int row = idx>>2, seg = idx&3;
        uint32_t off = PA_FULL + (uint32_t)buf*PWSTEP + (uint32_t)(row*80 + seg*16);
        const __nv_bfloat16* wr = W + (size_t)row*KP2 + c*BK + seg*8;
        cpa(sb + off,          wr);
        cpa(sb + off + 10240u, wr + 128);
    }
    cp_commit();
}

__global__ __launch_bounds__(256,2)
void projmma_kernel(const float* __restrict__ z, const float* __restrict__ mask_,
                    const float* __restrict__ lnw, const float* __restrict__ lnb,
                    const float* __restrict__ agb, const float* __restrict__ apb,
                    const float* __restrict__ bgb, const float* __restrict__ bpb,
                    const float* __restrict__ gb_)
{
    extern __shared__ char sm[];
    uint32_t sb = s2u(sm);
    float* ot = (float*)(sm + PA_FULL);   // overlays W stream region (dead between passes)

    int tid=threadIdx.x, wid=tid>>5, lane=tid&31;
    int wm=wid&1, wn=wid>>1;
    int t2 = blockIdx.x;
    const float* zrow = z + (size_t)t2*64*CH;

    // ---- prologue (ONCE): LN(z) 64 rows -> split bf16 into resident A-full ----
    {
        float4 w4 = *(const float4*)(lnw + lane*4);
        float4 b4 = *(const float4*)(lnb + lane*4);
        uint32_t abase = (uint32_t)(lane>>3)*10240u + (uint32_t)((lane&7)*8);
        #pragma unroll
        for (int rr=0; rr<8; ++rr){
            int r = wid*8 + rr;
            float4 v = *(const float4*)(zrow + (size_t)r*CH + lane*4);
            float s = v.x+v.y+v.z+v.w;
            float q = v.x*v.x+v.y*v.y+v.z*v.z+v.w*v.w;
            #pragma unroll
            for (int o=16;o>0;o>>=1){ s+=__shfl_xor_sync(0xffffffffu,s,o); q+=__shfl_xor_sync(0xffffffffu,q,o); }
            float mu=s*(1.f/128.f), var=q*(1.f/128.f)-mu*mu;
            float rs=rsqrtf(fmaxf(var,0.f)+EPSF);
            float n0=(v.x-mu)*rs*w4.x+b4.x, n1=(v.y-mu)*rs*w4.y+b4.y;
            float n2=(v.z-mu)*rs*w4.z+b4.z, n3=(v.w-mu)*rs*w4.w+b4.w;
            __nv_bfloat16 h0=__float2bfloat16(n0), h1=__float2bfloat16(n1);
            __nv_bfloat16 h2=__float2bfloat16(n2), h3=__float2bfloat16(n3);
            __nv_bfloat16 l0=__float2bfloat16(n0-__bfloat162float(h0));
            __nv_bfloat16 l1=__float2bfloat16(n1-__bfloat162float(h1));
            __nv_bfloat16 l2=__float2bfloat16(n2-__bfloat162float(h2));
            __nv_bfloat16 l3=__float2bfloat16(n3-__bfloat162float(h3));
            uint32_t off = abase + (uint32_t)(r*80);
            *(__nv_bfloat162*)(sm + off)          = __nv_bfloat162{h0,h1};
            *(__nv_bfloat162*)(sm + off + 4)      = __nv_bfloat162{h2,h3};
            *(__nv_bfloat162*)(sm + off + 5120)   = __nv_bfloat162{l0,l1};
            *(__nv_bfloat162*)(sm + off + 5124)   = __nv_bfloat162{l2,l3};
        }
    }
    __syncthreads();

    for (int ph=0; ph<3; ++ph){
        bool hasP = ph<2;
        const __nv_bfloat16* WG = g_ws + (size_t)(hasP ? 2*ph : 4)*CH*KP2;
        const __nv_bfloat16* WP = g_ws + (size_t)(hasP ? 2*ph+1 : 4)*CH*KP2;
        const float* GBp = (ph==0)?agb:((ph==1)?bgb:gb_);
        const float* PBp = (ph==0)?apb:bpb;

        float accG[2][4][4], accP[2][4][4];
        #pragma unroll
        for (int mf=0;mf<2;++mf)
            #pragma unroll
            for (int nf=0;nf<4;++nf)
                #pragma unroll
                for (int r=0;r<4;++r){ accG[mf][nf][r]=0.f; accP[mf][nf][r]=0.f; }

        // ---- pass G ----
        wissue(tid, 0, 0, sb, WG);
        for (int c=0; c<NCH_P; ++c){
            int buf = c & 1;
            if (c+1<NCH_P){ wissue(tid, c+1, buf^1, sb, WG); cp_wait<1>(); }
            else cp_wait<0>();
            __syncthreads();
            uint32_t abase = sb + (uint32_t)c*10240u;
            uint32_t wbase = sb + PA_FULL + (uint32_t)buf*PWSTEP;
            #pragma unroll
            for (int ks=0; ks<2; ++ks){
                uint32_t ah[2][4], al[2][4];
                #pragma unroll
                for (int mf=0; mf<2; ++mf){
                    int row = wm*32 + mf*16 + (lane&15);
                    int kc  = ks*16 + (lane>>4)*8;
                    uint32_t ro = (uint32_t)(row*LDW + kc)*2;
                    ldsm4(ah[mf][0],ah[mf][1],ah[mf][2],ah[mf][3], abase + ro);
                    ldsm4(al[mf][0],al[mf][1],al[mf][2],al[mf][3], abase + 5120u + ro);
                }
                uint32_t bf[4][2];
                ldB(wbase, wn, lane, ks, bf);            // Gh
                #pragma unroll
                for (int mf=0; mf<2; ++mf)
                    #pragma unroll
                    for (int nf=0; nf<4; ++nf){
                        mma16816(accG[mf][nf], ah[mf], bf[nf]);
                        mma16816(accG[mf][nf], al[mf], bf[nf]);
                    }
                ldB(wbase + 10240u, wn, lane, ks, bf);   // Gl
                #pragma unroll
                for (int mf=0; mf<2; ++mf)
                    #pragma unroll
                    for (int nf=0; nf<4; ++nf)
                        mma16816(accG[mf][nf], ah[mf], bf[nf]);
            }
            __syncthreads();
        }

        // ---- pass P (hasP phases only) ----
        if (hasP){
            wissue(tid, 0, 0, sb, WP);
            for (int c=0; c<NCH_P; ++c){
                int buf = c & 1;
                if (c+1<NCH_P){ wissue(tid, c+1, buf^1, sb, WP); cp_wait<1>(); }
                else cp_wait<0>();
                __syncthreads();
                uint32_t abase = sb + (uint32_t)c*10240u;
                uint32_t wbase = sb + PA_FULL + (uint32_t)buf*PWSTEP;
                #pragma unroll
                for (int ks=0; ks<2; ++ks){
                    uint32_t ah[2][4], al[2][4];
                    #pragma unroll
                    for (int mf=0; mf<2; ++mf){
                        int row = wm*32 + mf*16 + (lane&15);
                        int kc  = ks*16 + (lane>>4)*8;
                        uint32_t ro = (uint32_t)(row*LDW + kc)*2;
                        ldsm4(ah[mf][0],ah[mf][1],ah[mf][2],ah[mf][3], abase + ro);
                        ldsm4(al[mf][0],al[mf][1],al[mf][2],al[mf][3], abase + 5120u + ro);
                    }
                    uint32_t bf[4][2];
                    ldB(wbase, wn, lane, ks, bf);            // Ph
                    #pragma unroll
                    for (int mf=0; mf<2; ++mf)
                        #pragma unroll
                        for (int nf=0; nf<4; ++nf){
                            mma16816(accP[mf][nf], ah[mf], bf[nf]);
                            mma16816(accP[mf][nf], al[mf], bf[nf]);
                        }
                    ldB(wbase + 10240u, wn, lane, ks, bf);   // Pl
                    #pragma unroll
                    for (int mf=0; mf<2; ++mf)
                        #pragma unroll
                        for (int nf=0; nf<4; ++nf)
                            mma16816(accP[mf][nf], ah[mf], bf[nf]);
                }
                __syncthreads();
            }
        }

        // ---- epilogue ----
        if (hasP){
            __nv_bfloat16* dst = ph ? g_bs : g_as;
            int i_idx = t2/6, k0 = (t2%6)*64;
            #pragma unroll
            for (int mf=0; mf<2; ++mf)
                #pragma unroll
                for (int nf=0; nf<4; ++nf){
                    int col = wn*32 + nf*8 + (lane&3)*2;
                    int row = wm*32 + mf*16 + (lane>>2);
                    float mk0 = __ldg(mask_ + t2*64 + row);
                    float mk1 = __ldg(mask_ + t2*64 + row + 8);
                    float g0=__ldg(GBp+col), g1=__ldg(GBp+col+1);
                    float p0=__ldg(PBp+col), p1=__ldg(PBp+col+1);
                    ot[col*68+row]       = mk0*sigf(accG[mf][nf][0]+g0)*(accP[mf][nf][0]+p0);
                    ot[(col+1)*68+row]   = mk0*sigf(accG[mf][nf][1]+g1)*(accP[mf][nf][1]+p1);
                    ot[col*68+row+8]     = mk1*sigf(accG[mf][nf][2]+g0)*(accP[mf][nf][2]+p0);
                    ot[(col+1)*68+row+8] = mk1*sigf(accG[mf][nf][3]+g1)*(accP[mf][nf][3]+p1);
                }
            __syncthreads();
            #pragma unroll
            for (int it2=0; it2<32; ++it2){
                int f = tid + it2*256;
                int r = f&63, o = f>>6;
                float v = ot[o*68 + r];
                __nv_bfloat16 hi = __float2bfloat16(v);
                __nv_bfloat16 lo = __float2bfloat16(v - __bfloat162float(hi));
                size_t base = (size_t)o*(NRES*KS2) + (size_t)i_idx*KS2 + (k0 + r);
                dst[base]       = hi;
                dst[base + 384] = lo;
            }
            __syncthreads();   // ot region reused as W stream next phase
        } else {
            #pragma unroll
            for (int mf=0; mf<2; ++mf)
                #pragma unroll
                for (int nf=0; nf<4; ++nf){
                    int col = wn*32 + nf*8 + (lane&3)*2;
                    int row = wm*32 + mf*16 + (lane>>2);
                    size_t R0 = (size_t)t2*64 + row;
                    float g0=__ldg(GBp+col), g1=__ldg(GBp+col+1);
                    *(float2*)(g_gate + R0*CH + col) =
                        make_float2(sigf(accG[mf][nf][0]+g0), sigf(accG[mf][nf][1]+g1));
                    *(float2*)(g_gate + (R0+8)*CH + col) =
                        make_float2(sigf(accG[mf][nf][2]+g0), sigf(accG[mf][nf][3]+g1));
                }
        }
    }
}

// ================= tri (R9 form): per (h,i-tile,j-tile), 2-stage BK=32 =================
// stage regions: Ah 0, Al 10240, Bh 20480, Bl 30720
#define TSTEP 40960u
#define NCH_T 12

__device__ __forceinline__ void tri_issue(int tid, int c, int buf,
    const __nv_bfloat16* Ag, const __nv_bfloat16* Bg, uint32_t sb){
    int row2 = tid>>2, seg = tid&3;
    uint32_t bofs = (uint32_t)buf*TSTEP;
    #pragma unroll
    for (int it=0; it<2; ++it){
        int row = row2 + it*64;
        uint32_t off = bofs + (uint32_t)(row*80 + seg*16);
        const __nv_bfloat16* ar = Ag + (size_t)row*KS2 + c*BK + seg*8;
        cpa(sb + off,           ar);
        cpa(sb + 10240u + off,  ar+384);
        const __nv_bfloat16* br = Bg + (size_t)row*KS2 + c*BK + seg*8;
        cpa(sb + 20480u + off,  br);
        cpa(sb + 30720u + off,  br+384);
    }
    cp_commit();
}

__global__ __launch_bounds__(256,2)
void tri_mma_kernel(){
    extern __shared__ char sm[];
    uint32_t sb = s2u(sm);

    int tid = threadIdx.x;
    int wid = tid>>5, lane = tid&31;
    int wm = wid & 1, wn = wid >> 1;
    int h = blockIdx.z, i0 = blockIdx.y*128, j0 = blockIdx.x*128;

    const __nv_bfloat16* Ag = g_as + ((size_t)h*NRES + i0)*KS2;
    const __nv_bfloat16* Bg = g_bs + ((size_t)h*NRES + j0)*KS2;

    float acc[4][4][4];
    #pragma unroll
    for (int mf=0;mf<4;++mf)
        #pragma unroll
        for (int nf=0;nf<4;++nf)
            #pragma unroll
            for (int r=0;r<4;++r) acc[mf][nf][r]=0.f;

    tri_issue(tid, 0, 0, Ag, Bg, sb);

    for (int c=0; c<NCH_T; ++c){
        int buf = c & 1;
        if (c+1 < NCH_T){ tri_issue(tid, c+1, buf^1, Ag, Bg, sb); cp_wait<1>(); }
        else cp_wait<0>();
        __syncthreads();
        uint32_t bofs = sb + (uint32_t)buf*TSTEP;
        #pragma unroll
        for (int ks=0; ks<2; ++ks){
            uint32_t ah[4][4];
            #pragma unroll
            for (int mf=0; mf<4; ++mf){
                int row = wm*64 + mf*16 + (lane&15);
                int kc  = ks*16 + (lane>>4)*8;
                ldsm4(ah[mf][0],ah[mf][1],ah[mf][2],ah[mf][3], bofs + (uint32_t)(row*LDW + kc)*2);
            }
            uint32_t bh[4][2];
            ldB(bofs + 20480u, wn, lane, ks, bh);   // Bh
            #pragma unroll
            for (int mf=0; mf<4; ++mf)
                #pragma unroll
                for (int nf=0; nf<4; ++nf)
                    mma16816(acc[mf][nf], ah[mf], bh[nf]);
            {
                uint32_t bl[4][2];
                ldB(bofs + 30720u, wn, lane, ks, bl);  // Bl
                #pragma unroll
                for (int mf=0; mf<4; ++mf)
                    #pragma unroll
                    for (int nf=0; nf<4; ++nf)
                        mma16816(acc[mf][nf], ah[mf], bl[nf]);
            }
            #pragma unroll
            for (int mf=0; mf<4; ++mf){   // reuse ah regs for Al
                int row = wm*64 + mf*16 + (lane&15);
                int kc  = ks*16 + (lane>>4)*8;
                ldsm4(ah[mf][0],ah[mf][1],ah[mf][2],ah[mf][3], bofs + 10240u + (uint32_t)(row*LDW + kc)*2);
            }
            #pragma unroll
            for (int mf=0; mf<4; ++mf)
                #pragma unroll
                for (int nf=0; nf<4; ++nf)
                    mma16816(acc[mf][nf], ah[mf], bh[nf]);
        }
        __syncthreads();
    }

    float* X = g_xt + (size_t)h*NN;
    #pragma unroll
    for (int mf=0; mf<4; ++mf){
        #pragma unroll
        for (int nf=0; nf<4; ++nf){
            int row = i0 + wm*64 + mf*16 + (lane>>2);
            int col = j0 + wn*32 + nf*8 + (lane&3)*2;
            *(float2*)(X + (size_t)row*NRES + col)     = make_float2(acc[mf][nf][0], acc[mf][nf][1]);
            *(float2*)(X + (size_t)(row+8)*NRES + col) = make_float2(acc[mf][nf][2], acc[mf][nf][3]);
        }
    }
}

// ================= outmma (FUSED LN): out = gate * (LN(x) @ z_w^T + z_b) =================
// smem: A-full [0,40960): chunk c at c*10240 (Xh), +5120 (Xl); W db at 40960 + buf*20480
// xs prologue scratch (128x66 fp32 = 33792B) overlaps W region at 40960.
#define OA_FULL 40960u
#define OWSTEP 20480u

__device__ __forceinline__ void outw_issue(int tid, int c, int buf, uint32_t sb,
                                           const __nv_bfloat16* W){
    uint32_t bofs = OA_FULL + (uint32_t)buf*OWSTEP;
    #pragma unroll
    for (int it=0; it<2; ++it){
        int idx = tid + it*256;
        int row = idx>>2, seg = idx&3;
        uint32_t off = bofs + (uint32_t)(row*80 + seg*16);
        const __nv_bfloat16* wr = W + (size_t)row*KP2 + c*BK + seg*8;
        cpa(sb + off,          wr);
        cpa(sb + 10240u + off, wr+128);
    }
    cp_commit();
}

__global__ __launch_bounds__(256,2)
void outmma_kernel(const float* __restrict__ low, const float* __restrict__ lob,
                   const float* __restrict__ zb, float* __restrict__ out)
{
    extern __shared__ char sm[];
    uint32_t sb = s2u(sm);
    float* xs = (float*)(sm + OA_FULL);   // scratch, freed before W loads
    __shared__ float mu_s[64], rs_s[64], low_s[128], lob_s[128];

    int tid=threadIdx.x, wid=tid>>5, lane=tid&31;
    int wm=wid&1, wn=wid>>1;
    int t2 = blockIdx.x;
    int row0 = t2*64;

    if (tid<128){ low_s[tid]=low[tid]; lob_s[tid]=lob[tid]; }
    #pragma unroll
    for (int it=0; it<32; ++it){
        int f = tid + it*256;
        int r = f&63, h = f>>6;
        xs[h*66 + r] = g_xt[(size_t)h*NN + row0 + r];
    }
    __syncthreads();
    #pragma unroll
    for (int rr=0;rr<8;++rr){
        int r = wid*8+rr;
        float s=0.f,q=0.f;
        #pragma unroll
        for (int m=0;m<4;++m){ float x=xs[(lane+32*m)*66 + r]; s+=x; q+=x*x; }
        #pragma unroll
        for (int o=16;o>0;o>>=1){ s+=__shfl_xor_sync(0xffffffffu,s,o); q+=__shfl_xor_sync(0xffffffffu,q,o); }
        if (lane==0){
            float mu=s*(1.f/128.f), var=q*(1.f/128.f)-mu*mu;
            mu_s[r]=mu; rs_s[r]=rsqrtf(fmaxf(var,0.f)+EPSF);
        }
    }
    __syncthreads();
    #pragma unroll
    for (int it=0; it<16; ++it){
        int f = tid + it*256;
        int r = f>>6, h2 = (f&63)*2;
        float mu=mu_s[r], rs=rs_s[r];
        float x0 = (xs[(h2+0)*66+r]-mu)*rs*low_s[h2+0]+lob_s[h2+0];
        float x1 = (xs[(h2+1)*66+r]-mu)*rs*low_s[h2+1]+lob_s[h2+1];
        __nv_bfloat16 h0=__float2bfloat16(x0), h1=__float2bfloat16(x1);
        __nv_bfloat16 l0=__float2bfloat16(x0-__bfloat162float(h0));
        __nv_bfloat16 l1=__float2bfloat16(x1-__bfloat162float(h1));
        uint32_t off = (uint32_t)(h2>>5)*10240u + (uint32_t)(r*80 + (h2&31)*2);
        *(__nv_bfloat162*)(sm + off)          = __nv_bfloat162{h0,h1};
        *(__nv_bfloat162*)(sm + off + 5120u)  = __nv_bfloat162{l0,l1};
    }
    __syncthreads();   // A-full ready; xs region now free for W streaming

    const __nv_bfloat16* W = g_ws + (size_t)5*CH*KP2;
    float acc[2][4][4];
    #pragma unroll
    for (int mf=0;mf<2;++mf)
        #pragma unroll
        for (int nf=0;nf<4;++nf)
            #pragma unroll
            for (int r=0;r<4;++r) acc[mf][nf][r]=0.f;

    outw_issue(tid, 0, 0, sb, W);

    for (int c=0; c<NCH_P; ++c){
        int buf = c & 1;
        if (c+1<NCH_P){ outw_issue(tid, c+1, buf^1, sb, W); cp_wait<1>(); }
        else cp_wait<0>();
        __syncthreads();
        uint32_t abase = sb + (uint32_t)c*10240u;
        uint32_t wbase = sb + OA_FULL + (uint32_t)buf*OWSTEP;
        #pragma unroll
        for (int ks=0; ks<2; ++ks){
            uint32_t ah[2][4], al[2][4];
            #pragma unroll
            for (int mf=0; mf<2; ++mf){
                int row = wm*32 + mf*16 + (lane&15);
                int kc  = ks*16 + (lane>>4)*8;
                uint32_t ro = (uint32_t)(row*LDW + kc)*2;
                ldsm4(ah[mf][0],ah[mf][1],ah[mf][2],ah[mf][3], abase + ro);
                ldsm4(al[mf][0],al[mf][1],al[mf][2],al[mf][3], abase + 5120u + ro);
            }
            uint32_t bf[4][2];
            ldB(wbase, wn, lane, ks, bf);            // Wh
            #pragma unroll
            for (int mf=0; mf<2; ++mf)
                #pragma unroll
                for (int nf=0; nf<4; ++nf){
                    mma16816(acc[mf][nf], ah[mf], bf[nf]);
                    mma16816(acc[mf][nf], al[mf], bf[nf]);
                }
            ldB(wbase + 10240u, wn, lane, ks, bf);   // Wl
            #pragma unroll
            for (int mf=0; mf<2; ++mf)
                #pragma unroll
                for (int nf=0; nf<4; ++nf)
                    mma16816(acc[mf][nf], ah[mf], bf[nf]);
        }
        __syncthreads();
    }

    #pragma unroll
    for (int mf=0; mf<2; ++mf)
        #pragma unroll
        for (int nf=0; nf<4; ++nf){
            int col = wn*32 + nf*8 + (lane&3)*2;
            int row = wm*32 + mf*16 + (lane>>2);
            size_t R0 = (size_t)row0 + row;
            float2 zb2 = *(const float2*)(zb + col);
            float2 ga = *(const float2*)(g_gate + R0*CH + col);
            float2 gb2 = *(const float2*)(g_gate + (R0+8)*CH + col);
            *(float2*)(out + R0*CH + col) =
                make_float2(ga.x*(acc[mf][nf][0]+zb2.x), ga.y*(acc[mf][nf][1]+zb2.y));
            *(float2*)(out + (R0+8)*CH + col) =
                make_float2(gb2.x*(acc[mf][nf][2]+zb2.x), gb2.y*(acc[mf][nf][3]+zb2.y));
        }
}

extern "C" void kernel_launch(void* const* d_in, const int* in_sizes, int n_in,
                              void* d_out, int out_size) {
    const float* z      = (const float*)d_in[0];
    const float* mask   = (const float*)d_in[1];
    const float* ln_in_w= (const float*)d_in[2];
    const float* ln_in_b= (const float*)d_in[3];
    const float* a_g_w  = (const float*)d_in[4];
    const float* a_g_b  = (const float*)d_in[5];
    const float* a_p_w  = (const float*)d_in[6];
    const float* a_p_b  = (const float*)d_in[7];
    const float* b_g_w  = (const float*)d_in[8];
    const float* b_g_b  = (const float*)d_in[9];
    const float* b_p_w  = (const float*)d_in[10];
    const float* b_p_b  = (const float*)d_in[11];
    const float* g_w    = (const float*)d_in[12];
    const float* g_b    = (const float*)d_in[13];
    const float* ln_out_w=(const float*)d_in[14];
    const float* ln_out_b=(const float*)d_in[15];
    const float* z_w    = (const float*)d_in[16];
    const float* z_b    = (const float*)d_in[17];
    float* out = (float*)d_out;

    cudaFuncSetAttribute(projmma_kernel, cudaFuncAttributeMaxDynamicSharedMemorySize, 81920);
    cudaFuncSetAttribute(tri_mma_kernel, cudaFuncAttributeMaxDynamicSharedMemorySize, 2*TSTEP);
    cudaFuncSetAttribute(outmma_kernel, cudaFuncAttributeMaxDynamicSharedMemorySize, 81920);

    wsplit_kernel<<<6,256>>>(a_g_w, a_p_w, b_g_w, b_p_w, g_w, z_w);
    projmma_kernel<<<2304,256,81920>>>(z, mask, ln_in_w, ln_in_b,
                                       a_g_b, a_p_b, b_g_b, b_p_b, g_b);
    tri_mma_kernel<<<dim3(3,3,CH),256,2*TSTEP>>>();
    outmma_kernel<<<NN/64,256,81920>>>(ln_out_w, ln_out_b, z_b, out);
}